// round 1
// baseline (speedup 1.0000x reference)
#include <cuda_runtime.h>
#include <math.h>

#define EE 1024
#define HN 16
#define HDIM 64
#define DI 64
#define BB 2
#define TT 2048
#define NROW (BB*TT)   // 4096
#define G3 192

// ---------------- scratch (static device memory; no allocations) -------------
__device__ float g_cat_q[NROW*EE];
__device__ float g_cat_k[NROW*EE];
__device__ float g_xw_q[NROW*G3];
__device__ float g_xw_k[NROW*G3];
__device__ float g_vh[BB*HN*TT*HDIM];
__device__ float g_qpre[NROW*EE];
__device__ float g_kpre[NROW*EE];
__device__ float g_qh[BB*HN*TT*HDIM];
__device__ float g_kh[BB*HN*TT*HDIM];
__device__ float g_ao[NROW*EE];

// ---------------- kernel 1: fused prep -----------------------------------
// per row (b,t): v = silu(x)*v_emb[tok] (head-major), xs = pool16(x),
// xw_{q,k} = xs @ wih^T, xproj -> cat[:,64:]
__global__ void __launch_bounds__(256) prep_kernel(
    const float* __restrict__ x, const int* __restrict__ tok,
    const float* __restrict__ vemb,
    const float* __restrict__ qwih, const float* __restrict__ kwih)
{
    __shared__ float xsh[EE];
    __shared__ float xs[DI];
    int row = blockIdx.x;
    int tid = threadIdx.x;
    int b = row >> 11, t = row & (TT-1);

    ((float4*)xsh)[tid] = ((const float4*)(x + (long)row*EE))[tid];
    __syncthreads();

    // v = silu(x) * v_emb[tok], write head-major [BH, T, 64]
    int tk = tok[row];
    const float* ve = vemb + (long)tk*EE;
    for (int c = tid; c < EE; c += 256) {
        float xc = xsh[c];
        float s = xc / (1.f + expf(-xc));
        float val = s * ve[c];
        int h = c >> 6, d = c & 63;
        g_vh[((long)(b*HN + h)*TT + t)*HDIM + d] = val;
    }

    // pooled pos input (1024 -> 64, mean of 16)
    if (tid < DI) {
        float s = 0.f;
        #pragma unroll
        for (int i = 0; i < 16; i++) s += xsh[tid*16 + i];
        xs[tid] = s * (1.f/16.f);
    }
    __syncthreads();

    // xw for both paths: [192] dots of length 64
    for (int idx = tid; idx < 2*G3; idx += 256) {
        int path = idx / G3, g = idx - path*G3;
        const float* w = (path ? kwih : qwih) + g*DI;
        float a0=0.f, a1=0.f, a2=0.f, a3=0.f;
        #pragma unroll
        for (int d = 0; d < DI; d += 4) {
            a0 += xs[d+0]*w[d+0];
            a1 += xs[d+1]*w[d+1];
            a2 += xs[d+2]*w[d+2];
            a3 += xs[d+3]*w[d+3];
        }
        float acc = (a0+a1)+(a2+a3);
        (path ? g_xw_k : g_xw_q)[(long)row*G3 + g] = acc;
    }

    // xproj (1024 -> 960 adaptive pool): out[j] = mean(x[floor(16j/15) : ceil(16(j+1)/15)])
    for (int j = tid; j < EE - DI; j += 256) {
        int s0 = (j*16)/15;
        int e0 = ((j+1)*16 + 14)/15;
        float s = 0.f;
        for (int c = s0; c < e0; c++) s += xsh[c];
        s *= 1.f/(float)(e0 - s0);
        g_cat_q[(long)row*EE + DI + j] = s;
        g_cat_k[(long)row*EE + DI + j] = s;
    }
}

// ---------------- kernel 2: GRU recurrence --------------------------------
// grid = 4 (path x batch), 192 threads. Thread g computes hw[g] = h . whh[g].
// Gates: r,z get xw folded in; n-gate keeps xw separate (r scales hw_n only).
__global__ void __launch_bounds__(192) gru_kernel(
    const float* __restrict__ qwhh, const float* __restrict__ kwhh)
{
    int path = blockIdx.x >> 1;
    int b = blockIdx.x & 1;
    int g = threadIdx.x;  // 0..191
    const float* whh = (path ? kwhh : qwhh) + g*DI;
    const float* xw  = (path ? g_xw_k : g_xw_q);
    float* cat = (path ? g_cat_k : g_cat_q);

    float4 w[16];
    #pragma unroll
    for (int i = 0; i < 16; i++) w[i] = ((const float4*)whh)[i];

    __shared__ float h_sh[DI];
    __shared__ float hw_sh[G3];
    if (g < DI) h_sh[g] = 0.f;
    __syncthreads();

    for (int t = 0; t < TT; t++) {
        long row = (long)b*TT + t;
        float acc[4];
        acc[0] = (g < 128) ? xw[row*G3 + g] : 0.f;
        acc[1] = 0.f; acc[2] = 0.f; acc[3] = 0.f;
        #pragma unroll
        for (int i = 0; i < 16; i++) {
            float4 hv = ((const float4*)h_sh)[i];
            float4 wv = w[i];
            acc[i & 3] += hv.x*wv.x + hv.y*wv.y + hv.z*wv.z + hv.w*wv.w;
        }
        hw_sh[g] = (acc[0]+acc[1]) + (acc[2]+acc[3]);
        __syncthreads();
        if (g < DI) {
            float r = 1.f/(1.f + expf(-hw_sh[g]));
            float z = 1.f/(1.f + expf(-hw_sh[DI + g]));
            float xwn = xw[row*G3 + 128 + g];
            float n = tanhf(xwn + r*hw_sh[128 + g]);
            float hn = (1.f - z)*n + z*h_sh[g];
            h_sh[g] = hn;
            cat[row*EE + g] = hn;
        }
        __syncthreads();
    }
}

// ---------------- kernel 3: SGEMM  C = A @ W^T (+res) (+bias) -------------
// A: [M,K] row-major, W: [N,K] row-major. BM=BN=128, BK=8, 256 thr, 8x8 tiles.
__global__ void __launch_bounds__(256) sgemm_kernel(
    const float* __restrict__ A, const float* __restrict__ W,
    const float* __restrict__ res, const float* __restrict__ bias,
    float* __restrict__ C, int M, int N, int K)
{
    __shared__ float As[8][128];
    __shared__ float Ws[8][128];
    int tid = threadIdx.x;
    int m0 = blockIdx.y * 128, n0 = blockIdx.x * 128;
    int lr = tid >> 1;            // 0..127
    int lk = (tid & 1) * 4;
    const float* Ap = A + (long)(m0 + lr)*K + lk;
    const float* Wp = W + (long)(n0 + lr)*K + lk;
    int ty = tid >> 4, tx = tid & 15;

    float acc[8][8] = {};
    for (int k0 = 0; k0 < K; k0 += 8) {
        float4 av = *(const float4*)(Ap + k0);
        float4 wv = *(const float4*)(Wp + k0);
        As[lk+0][lr] = av.x; As[lk+1][lr] = av.y; As[lk+2][lr] = av.z; As[lk+3][lr] = av.w;
        Ws[lk+0][lr] = wv.x; Ws[lk+1][lr] = wv.y; Ws[lk+2][lr] = wv.z; Ws[lk+3][lr] = wv.w;
        __syncthreads();
        #pragma unroll
        for (int kk = 0; kk < 8; kk++) {
            float a[8], wr[8];
            #pragma unroll
            for (int i = 0; i < 8; i++) a[i] = As[kk][ty*8 + i];
            #pragma unroll
            for (int j = 0; j < 8; j++) wr[j] = Ws[kk][tx*8 + j];
            #pragma unroll
            for (int i = 0; i < 8; i++)
                #pragma unroll
                for (int j = 0; j < 8; j++)
                    acc[i][j] += a[i]*wr[j];
        }
        __syncthreads();
    }
    #pragma unroll
    for (int i = 0; i < 8; i++) {
        long m = m0 + ty*8 + i;
        #pragma unroll
        for (int j = 0; j < 8; j++) {
            long n = n0 + tx*8 + j;
            float v = acc[i][j];
            if (res)  v += res[m*N + n];
            if (bias) v += bias[n];
            C[m*N + n] = v;
        }
    }
}

// ---------------- kernel 4: LayerNorm -> head-major -----------------------
__global__ void __launch_bounds__(256) ln_kernel(
    const float* __restrict__ wq, const float* __restrict__ bq,
    const float* __restrict__ wk, const float* __restrict__ bk)
{
    int idx = blockIdx.x;
    int path = idx >> 12;
    int row = idx & 4095;
    const float* src = (path ? g_kpre : g_qpre) + (long)row*EE;
    const float* w = path ? wk : wq;
    const float* bb = path ? bk : bq;
    float* dst = path ? g_kh : g_qh;
    int tid = threadIdx.x;

    float4 v = ((const float4*)src)[tid];
    float s  = v.x + v.y + v.z + v.w;
    float sq = v.x*v.x + v.y*v.y + v.z*v.z + v.w*v.w;
    #pragma unroll
    for (int o = 16; o; o >>= 1) {
        s  += __shfl_xor_sync(0xffffffffu, s,  o);
        sq += __shfl_xor_sync(0xffffffffu, sq, o);
    }
    __shared__ float ss[8], sqs[8];
    __shared__ float mu_s, r_s;
    if ((tid & 31) == 0) { ss[tid >> 5] = s; sqs[tid >> 5] = sq; }
    __syncthreads();
    if (tid == 0) {
        float S = 0.f, SQ = 0.f;
        #pragma unroll
        for (int i = 0; i < 8; i++) { S += ss[i]; SQ += sqs[i]; }
        float mu = S * (1.f/EE);
        float var = SQ * (1.f/EE) - mu*mu;
        mu_s = mu;
        r_s = rsqrtf(var + 1e-5f);
    }
    __syncthreads();
    float mu = mu_s, r = r_s;
    int b = row >> 11, t = row & (TT-1);
    int c0 = tid * 4;
    int h = c0 >> 6, d = c0 & 63;
    float4 o;
    o.x = (v.x - mu)*r*w[c0+0] + bb[c0+0];
    o.y = (v.y - mu)*r*w[c0+1] + bb[c0+1];
    o.z = (v.z - mu)*r*w[c0+2] + bb[c0+2];
    o.w = (v.w - mu)*r*w[c0+3] + bb[c0+3];
    *(float4*)&dst[((long)(b*HN + h)*TT + t)*HDIM + d] = o;
}

// ---------------- kernel 5: causal attention (flash style) ----------------
// grid (16 q-blocks, 32 bh), 128 threads; thread owns one q row.
// scores = (q.k)*0.25 (the *2 doubling folded into 1/sqrt(64)); causal mask.
__global__ void __launch_bounds__(128) attn_kernel()
{
    int qblk = blockIdx.x, bh = blockIdx.y;
    int tid = threadIdx.x;
    int t = qblk*128 + tid;

    const float* qp = g_qh + ((long)bh*TT + t)*HDIM;
    float q[64];
    #pragma unroll
    for (int i = 0; i < 16; i++) {
        float4 v = ((const float4*)qp)[i];
        q[4*i+0] = v.x; q[4*i+1] = v.y; q[4*i+2] = v.z; q[4*i+3] = v.w;
    }
    float O[64];
    #pragma unroll
    for (int d = 0; d < 64; d++) O[d] = 0.f;
    float m = -1e30f, l = 0.f;

    __shared__ float ks[32*64];
    __shared__ float vs[32*64];
    const float* kbase = g_kh + (long)bh*TT*HDIM;
    const float* vbase = g_vh + (long)bh*TT*HDIM;

    int nchunk = (qblk + 1) * 4;
    for (int c = 0; c < nchunk; c++) {
        int s0 = c * 32;
        #pragma unroll
        for (int qd = 0; qd < 4; qd++) {
            int f = tid + qd*128;  // float4 index 0..511
            ((float4*)ks)[f] = ((const float4*)(kbase + (long)s0*HDIM))[f];
            ((float4*)vs)[f] = ((const float4*)(vbase + (long)s0*HDIM))[f];
        }
        __syncthreads();
        if (s0 <= t) {
            float sc[32];
            float mloc = -1e30f;
            #pragma unroll 2
            for (int j = 0; j < 32; j++) {
                int sg = s0 + j;
                const float* kr = ks + j*64;
                float a0=0.f, a1=0.f, a2=0.f, a3=0.f;
                #pragma unroll
                for (int d = 0; d < 64; d += 4) {
                    a0 += q[d+0]*kr[d+0];
                    a1 += q[d+1]*kr[d+1];
                    a2 += q[d+2]*kr[d+2];
                    a3 += q[d+3]*kr[d+3];
                }
                float dt = (a0+a1)+(a2+a3);
                sc[j] = (sg <= t) ? dt*0.25f : -1e30f;
                mloc = fmaxf(mloc, sc[j]);
            }
            float mnew = fmaxf(m, mloc);
            float corr = __expf(m - mnew);
            l *= corr;
            #pragma unroll
            for (int d = 0; d < 64; d++) O[d] *= corr;
            #pragma unroll 2
            for (int j = 0; j < 32; j++) {
                float p = __expf(sc[j] - mnew);
                l += p;
                const float* vr = vs + j*64;
                #pragma unroll
                for (int d = 0; d < 64; d++) O[d] += p*vr[d];
            }
            m = mnew;
        }
        __syncthreads();
    }

    int b = bh >> 4, h = bh & 15;
    float* op = g_ao + ((long)(b*TT + t))*EE + h*HDIM;
    float inv = 1.f / l;
    #pragma unroll
    for (int d = 0; d < 64; d++) op[d] = O[d]*inv;
}

// ---------------- launch ---------------------------------------------------
extern "C" void kernel_launch(void* const* d_in, const int* in_sizes, int n_in,
                              void* d_out, int out_size)
{
    const float* x     = (const float*)d_in[0];
    const int*   tok   = (const int*)  d_in[1];
    const float* qwih  = (const float*)d_in[2];
    const float* qwhh  = (const float*)d_in[3];
    const float* qlinw = (const float*)d_in[4];
    const float* kwih  = (const float*)d_in[5];
    const float* kwhh  = (const float*)d_in[6];
    const float* klinw = (const float*)d_in[7];
    const float* vemb  = (const float*)d_in[8];
    const float* qlnw  = (const float*)d_in[9];
    const float* qlnb  = (const float*)d_in[10];
    const float* klnw  = (const float*)d_in[11];
    const float* klnb  = (const float*)d_in[12];
    const float* outw  = (const float*)d_in[13];
    const float* outb  = (const float*)d_in[14];
    float* out = (float*)d_out;

    float *cat_q, *cat_k, *qpre, *kpre, *ao;
    cudaGetSymbolAddress((void**)&cat_q, g_cat_q);
    cudaGetSymbolAddress((void**)&cat_k, g_cat_k);
    cudaGetSymbolAddress((void**)&qpre,  g_qpre);
    cudaGetSymbolAddress((void**)&kpre,  g_kpre);
    cudaGetSymbolAddress((void**)&ao,    g_ao);

    prep_kernel<<<NROW, 256>>>(x, tok, vemb, qwih, kwih);
    gru_kernel<<<4, 192>>>(qwhh, kwhh);
    sgemm_kernel<<<dim3(EE/128, NROW/128), 256>>>(cat_q, qlinw, x, nullptr, qpre, NROW, EE, EE);
    sgemm_kernel<<<dim3(EE/128, NROW/128), 256>>>(cat_k, klinw, x, nullptr, kpre, NROW, EE, EE);
    ln_kernel<<<2*NROW, 256>>>(qlnw, qlnb, klnw, klnb);
    attn_kernel<<<dim3(TT/128, BB*HN), 128>>>();
    sgemm_kernel<<<dim3(EE/128, NROW/128), 256>>>(ao, outw, nullptr, outb, out, NROW, EE, EE);
}

// round 2
// speedup vs baseline: 1.3477x; 1.3477x over previous
#include <cuda_runtime.h>
#include <math.h>

#define EE 1024
#define HN 16
#define HDIM 64
#define DI 64
#define BB 2
#define TT 2048
#define NROW (BB*TT)   // 4096
#define G3 192

// ---------------- scratch (static device memory) ---------------------------
__device__ float g_cat_q[NROW*EE];
__device__ float g_cat_k[NROW*EE];
__device__ float g_xw_q[NROW*G3];
__device__ float g_xw_k[NROW*G3];
__device__ float g_vh[BB*HN*TT*HDIM];   // [bh][t][d]
__device__ float g_qpre[NROW*EE];
__device__ float g_kpre[NROW*EE];
__device__ float g_mu[2*NROW];
__device__ float g_rs[2*NROW];
__device__ float g_qt[BB*HN*HDIM*TT];   // [bh][d][t]
__device__ float g_kt[BB*HN*HDIM*TT];   // [bh][d][t]
__device__ float g_ao[NROW*EE];

// ---------------- kernel 1: fused prep -------------------------------------
__global__ void __launch_bounds__(256) prep_kernel(
    const float* __restrict__ x, const int* __restrict__ tok,
    const float* __restrict__ vemb,
    const float* __restrict__ qwih, const float* __restrict__ kwih)
{
    __shared__ float xsh[EE];
    __shared__ float xs[DI];
    int row = blockIdx.x;
    int tid = threadIdx.x;
    int b = row >> 11, t = row & (TT-1);

    ((float4*)xsh)[tid] = ((const float4*)(x + (long)row*EE))[tid];
    __syncthreads();

    int tk = tok[row];
    const float* ve = vemb + (long)tk*EE;
    for (int c = tid; c < EE; c += 256) {
        float xc = xsh[c];
        float s = xc / (1.f + __expf(-xc));
        float val = s * ve[c];
        int h = c >> 6, d = c & 63;
        g_vh[((long)(b*HN + h)*TT + t)*HDIM + d] = val;
    }

    if (tid < DI) {
        float s = 0.f;
        #pragma unroll
        for (int i = 0; i < 16; i++) s += xsh[tid*16 + i];
        xs[tid] = s * (1.f/16.f);
    }
    __syncthreads();

    for (int idx = tid; idx < 2*G3; idx += 256) {
        int path = idx / G3, g = idx - path*G3;
        const float* w = (path ? kwih : qwih) + g*DI;
        float a0=0.f, a1=0.f, a2=0.f, a3=0.f;
        #pragma unroll
        for (int d = 0; d < DI; d += 4) {
            a0 += xs[d+0]*w[d+0];
            a1 += xs[d+1]*w[d+1];
            a2 += xs[d+2]*w[d+2];
            a3 += xs[d+3]*w[d+3];
        }
        float acc = (a0+a1)+(a2+a3);
        (path ? g_xw_k : g_xw_q)[(long)row*G3 + g] = acc;
    }

    for (int j = tid; j < EE - DI; j += 256) {
        int s0 = (j*16)/15;
        int e0 = ((j+1)*16 + 14)/15;
        float s = 0.f;
        for (int c = s0; c < e0; c++) s += xsh[c];
        s *= 1.f/(float)(e0 - s0);
        g_cat_q[(long)row*EE + DI + j] = s;
        g_cat_k[(long)row*EE + DI + j] = s;
    }
}

// ---------------- kernel 2: GRU recurrence ---------------------------------
__global__ void __launch_bounds__(192) gru_kernel(
    const float* __restrict__ qwhh, const float* __restrict__ kwhh)
{
    int path = blockIdx.x >> 1;
    int b = blockIdx.x & 1;
    int g = threadIdx.x;  // 0..191
    const float* whh = (path ? kwhh : qwhh) + g*DI;
    const float* xw  = (path ? g_xw_k : g_xw_q);
    float* cat = (path ? g_cat_k : g_cat_q);

    float4 w[16];
    #pragma unroll
    for (int i = 0; i < 16; i++) w[i] = ((const float4*)whh)[i];

    __shared__ float h_sh[DI];
    __shared__ float hw_sh[G3];
    __shared__ float xwn_sh[DI];
    if (g < DI) h_sh[g] = 0.f;
    __syncthreads();

    long base = (long)b*TT*G3 + g;
    float xwp = xw[base];  // t=0 prefetch
    for (int t = 0; t < TT; t++) {
        float xw_cur = xwp;
        if (t+1 < TT) xwp = xw[base + (long)(t+1)*G3];  // prefetch next

        float acc[4] = {0.f, 0.f, 0.f, 0.f};
        #pragma unroll
        for (int i = 0; i < 16; i++) {
            float4 hv = ((const float4*)h_sh)[i];
            float4 wv = w[i];
            acc[i & 3] += hv.x*wv.x + hv.y*wv.y + hv.z*wv.z + hv.w*wv.w;
        }
        float hwraw = (acc[0]+acc[1]) + (acc[2]+acc[3]);
        hw_sh[g] = hwraw + ((g < 128) ? xw_cur : 0.f);
        if (g >= 128) xwn_sh[g - 128] = xw_cur;
        __syncthreads();
        if (g < DI) {
            float r = 1.f/(1.f + __expf(-hw_sh[g]));
            float z = 1.f/(1.f + __expf(-hw_sh[DI + g]));
            float n = __tanhf(xwn_sh[g] + r*hw_sh[128 + g]);
            float hn = (1.f - z)*n + z*h_sh[g];
            h_sh[g] = hn;
            cat[((long)b*TT + t)*EE + g] = hn;
        }
        __syncthreads();
    }
}

// ---------------- SGEMM body: C = A @ W^T (+res) (+bias) -------------------
__device__ __forceinline__ void sgemm_body(
    const float* __restrict__ A, const float* __restrict__ W,
    const float* __restrict__ res, const float* __restrict__ bias,
    float* __restrict__ C, int N, int K)
{
    __shared__ float As[8][128];
    __shared__ float Ws[8][128];
    int tid = threadIdx.x;
    int m0 = blockIdx.y * 128, n0 = blockIdx.x * 128;
    int lr = tid >> 1;
    int lk = (tid & 1) * 4;
    const float* Ap = A + (long)(m0 + lr)*K + lk;
    const float* Wp = W + (long)(n0 + lr)*K + lk;
    int ty = tid >> 4, tx = tid & 15;

    float acc[8][8] = {};
    for (int k0 = 0; k0 < K; k0 += 8) {
        float4 av = *(const float4*)(Ap + k0);
        float4 wv = *(const float4*)(Wp + k0);
        As[lk+0][lr] = av.x; As[lk+1][lr] = av.y; As[lk+2][lr] = av.z; As[lk+3][lr] = av.w;
        Ws[lk+0][lr] = wv.x; Ws[lk+1][lr] = wv.y; Ws[lk+2][lr] = wv.z; Ws[lk+3][lr] = wv.w;
        __syncthreads();
        #pragma unroll
        for (int kk = 0; kk < 8; kk++) {
            float a[8], wr[8];
            #pragma unroll
            for (int i = 0; i < 8; i++) a[i] = As[kk][ty*8 + i];
            #pragma unroll
            for (int j = 0; j < 8; j++) wr[j] = Ws[kk][tx*8 + j];
            #pragma unroll
            for (int i = 0; i < 8; i++)
                #pragma unroll
                for (int j = 0; j < 8; j++)
                    acc[i][j] += a[i]*wr[j];
        }
        __syncthreads();
    }
    #pragma unroll
    for (int i = 0; i < 8; i++) {
        long m = m0 + ty*8 + i;
        #pragma unroll
        for (int j = 0; j < 8; j++) {
            long n = n0 + tx*8 + j;
            float v = acc[i][j];
            if (res)  v += res[m*N + n];
            if (bias) v += bias[n];
            C[m*N + n] = v;
        }
    }
}

__global__ void __launch_bounds__(256) sgemm_qk_kernel(
    const float* __restrict__ x,
    const float* __restrict__ qW, const float* __restrict__ kW)
{
    int z = blockIdx.z;
    sgemm_body(z ? g_cat_k : g_cat_q, z ? kW : qW, x, nullptr,
               z ? g_kpre : g_qpre, EE, EE);
}

__global__ void __launch_bounds__(256) sgemm_out_kernel(
    const float* __restrict__ W, const float* __restrict__ bias,
    float* __restrict__ C)
{
    sgemm_body(g_ao, W, nullptr, bias, C, EE, EE);
}

// ---------------- LayerNorm stats ------------------------------------------
__global__ void __launch_bounds__(256) ln_stats_kernel()
{
    int idx = blockIdx.x;            // path*4096 + row
    int path = idx >> 12;
    int row = idx & 4095;
    const float* src = (path ? g_kpre : g_qpre) + (long)row*EE;
    int tid = threadIdx.x;

    float4 v = ((const float4*)src)[tid];
    float s  = v.x + v.y + v.z + v.w;
    float sq = v.x*v.x + v.y*v.y + v.z*v.z + v.w*v.w;
    #pragma unroll
    for (int o = 16; o; o >>= 1) {
        s  += __shfl_xor_sync(0xffffffffu, s,  o);
        sq += __shfl_xor_sync(0xffffffffu, sq, o);
    }
    __shared__ float ss[8], sqs[8];
    if ((tid & 31) == 0) { ss[tid >> 5] = s; sqs[tid >> 5] = sq; }
    __syncthreads();
    if (tid == 0) {
        float S = 0.f, SQ = 0.f;
        #pragma unroll
        for (int i = 0; i < 8; i++) { S += ss[i]; SQ += sqs[i]; }
        float mu = S * (1.f/EE);
        float var = SQ * (1.f/EE) - mu*mu;
        g_mu[idx] = mu;
        g_rs[idx] = rsqrtf(var + 1e-5f);
    }
}

// ---------------- LN apply + transpose to [bh][d][t] -----------------------
__global__ void __launch_bounds__(256) lnt_kernel(
    const float* __restrict__ wq, const float* __restrict__ bq,
    const float* __restrict__ wk, const float* __restrict__ bk)
{
    int path = blockIdx.z;
    int bh = blockIdx.y;          // 0..31
    int tc = blockIdx.x;          // 0..31
    int b = bh >> 4, h = bh & 15;
    const float* src = path ? g_kpre : g_qpre;
    const float* w  = path ? wk : wq;
    const float* bi = path ? bk : bq;
    float* dst = path ? g_kt : g_qt;
    __shared__ float tile[64*65];
    int tid = threadIdx.x;
    int t0 = tc*64;

    #pragma unroll
    for (int ff = 0; ff < 4; ff++) {
        int f = tid + ff*256;
        int tl = f >> 4, c4 = f & 15;
        int row = b*TT + t0 + tl;
        float mu = g_mu[path*NROW + row];
        float rs = g_rs[path*NROW + row];
        float4 v = *(const float4*)(src + (long)row*EE + h*64 + c4*4);
        int c = c4*4;
        tile[(c+0)*65 + tl] = (v.x-mu)*rs*w[h*64+c+0] + bi[h*64+c+0];
        tile[(c+1)*65 + tl] = (v.y-mu)*rs*w[h*64+c+1] + bi[h*64+c+1];
        tile[(c+2)*65 + tl] = (v.z-mu)*rs*w[h*64+c+2] + bi[h*64+c+2];
        tile[(c+3)*65 + tl] = (v.w-mu)*rs*w[h*64+c+3] + bi[h*64+c+3];
    }
    __syncthreads();
    #pragma unroll
    for (int ff = 0; ff < 4; ff++) {
        int f = tid + ff*256;
        int cl = f >> 4, t4 = f & 15;
        float4 o;
        o.x = tile[cl*65 + t4*4+0];
        o.y = tile[cl*65 + t4*4+1];
        o.z = tile[cl*65 + t4*4+2];
        o.w = tile[cl*65 + t4*4+3];
        *(float4*)(dst + ((long)(bh*64 + cl))*TT + t0 + t4*4) = o;
    }
}

// ---------------- kernel 5: block-tiled flash attention --------------------
// Br=64 q rows, Bc=64 kv cols, 256 threads, 4x4 register tiles.
// Q/K in smem d-major ([d][r]); V s-major ([s][d]); P r-major ([r][s]).
__global__ void __launch_bounds__(256) attn2_kernel()
{
    extern __shared__ float sm[];
    float* Qs = sm;            // [64][64] Qs[d*64 + r]
    float* Ks = sm + 4096;     // [64][64] Ks[d*64 + s]
    float* Vs = sm + 8192;     // [64][64] Vs[s*64 + d]
    float* Ps = sm + 12288;    // [64][64] Ps[r*64 + s]

    int bh = blockIdx.y;
    int qblk = gridDim.x - 1 - blockIdx.x;   // longest blocks first
    int tid = threadIdx.x;
    int tx = tid & 15, ty = tid >> 4;
    int qr0 = qblk * 64;

    const float* qt = g_qt + (long)bh*HDIM*TT;   // [d][t]
    const float* kt = g_kt + (long)bh*HDIM*TT;   // [d][t]
    const float* vt = g_vh + (long)bh*TT*HDIM;   // [t][d]

    #pragma unroll
    for (int ff = 0; ff < 4; ff++) {
        int f = tid + ff*256;
        int d = f >> 4, c4 = f & 15;
        *(float4*)(Qs + d*64 + c4*4) = *(const float4*)(qt + (long)d*TT + qr0 + c4*4);
    }

    float O[4][4] = {};
    float m[4], l[4];
    #pragma unroll
    for (int i = 0; i < 4; i++) { m[i] = -1e30f; l[i] = 0.f; }

    int nchunk = qblk + 1;
    for (int c = 0; c < nchunk; c++) {
        int s0 = c * 64;
        __syncthreads();   // protect Ks/Vs (and first-iter Qs) from prior readers
        #pragma unroll
        for (int ff = 0; ff < 4; ff++) {
            int f = tid + ff*256;
            int d = f >> 4, c4 = f & 15;
            *(float4*)(Ks + d*64 + c4*4) = *(const float4*)(kt + (long)d*TT + s0 + c4*4);
            *(float4*)(Vs + d*64 + c4*4) = *(const float4*)(vt + (long)(s0 + d)*HDIM + c4*4);
        }
        __syncthreads();

        // S = 0.25 * Q.K^T   (the reference's x2 folded into 1/sqrt(64))
        float S[4][4] = {};
        #pragma unroll 8
        for (int d = 0; d < 64; d++) {
            float4 a = *(const float4*)(Qs + d*64 + ty*4);
            float4 bv = *(const float4*)(Ks + d*64 + tx*4);
            S[0][0] += a.x*bv.x; S[0][1] += a.x*bv.y; S[0][2] += a.x*bv.z; S[0][3] += a.x*bv.w;
            S[1][0] += a.y*bv.x; S[1][1] += a.y*bv.y; S[1][2] += a.y*bv.z; S[1][3] += a.y*bv.w;
            S[2][0] += a.z*bv.x; S[2][1] += a.z*bv.y; S[2][2] += a.z*bv.z; S[2][3] += a.z*bv.w;
            S[3][0] += a.w*bv.x; S[3][1] += a.w*bv.y; S[3][2] += a.w*bv.z; S[3][3] += a.w*bv.w;
        }

        bool diag = (c == qblk);
        #pragma unroll
        for (int i = 0; i < 4; i++) {
            int tg = qr0 + ty*4 + i;
            #pragma unroll
            for (int j = 0; j < 4; j++) {
                float v = S[i][j]*0.25f;
                if (diag && (s0 + tx*4 + j) > tg) v = -1e30f;
                S[i][j] = v;
            }
        }

        #pragma unroll
        for (int i = 0; i < 4; i++) {
            float mx = fmaxf(fmaxf(S[i][0], S[i][1]), fmaxf(S[i][2], S[i][3]));
            mx = fmaxf(mx, __shfl_xor_sync(0xffffffffu, mx, 1, 16));
            mx = fmaxf(mx, __shfl_xor_sync(0xffffffffu, mx, 2, 16));
            mx = fmaxf(mx, __shfl_xor_sync(0xffffffffu, mx, 4, 16));
            mx = fmaxf(mx, __shfl_xor_sync(0xffffffffu, mx, 8, 16));
            float mn = fmaxf(m[i], mx);
            float corr = __expf(m[i] - mn);
            float p0 = __expf(S[i][0]-mn), p1 = __expf(S[i][1]-mn);
            float p2 = __expf(S[i][2]-mn), p3 = __expf(S[i][3]-mn);
            float ps = (p0+p1)+(p2+p3);
            ps += __shfl_xor_sync(0xffffffffu, ps, 1, 16);
            ps += __shfl_xor_sync(0xffffffffu, ps, 2, 16);
            ps += __shfl_xor_sync(0xffffffffu, ps, 4, 16);
            ps += __shfl_xor_sync(0xffffffffu, ps, 8, 16);
            l[i] = l[i]*corr + ps;
            m[i] = mn;
            #pragma unroll
            for (int j = 0; j < 4; j++) O[i][j] *= corr;
            *(float4*)(Ps + (ty*4 + i)*64 + tx*4) = make_float4(p0, p1, p2, p3);
        }
        __syncthreads();

        // O += P @ V
        #pragma unroll 4
        for (int s = 0; s < 64; s++) {
            float4 bv = *(const float4*)(Vs + s*64 + tx*4);
            float a0 = Ps[(ty*4+0)*64 + s];
            float a1 = Ps[(ty*4+1)*64 + s];
            float a2 = Ps[(ty*4+2)*64 + s];
            float a3 = Ps[(ty*4+3)*64 + s];
            O[0][0] += a0*bv.x; O[0][1] += a0*bv.y; O[0][2] += a0*bv.z; O[0][3] += a0*bv.w;
            O[1][0] += a1*bv.x; O[1][1] += a1*bv.y; O[1][2] += a1*bv.z; O[1][3] += a1*bv.w;
            O[2][0] += a2*bv.x; O[2][1] += a2*bv.y; O[2][2] += a2*bv.z; O[2][3] += a2*bv.w;
            O[3][0] += a3*bv.x; O[3][1] += a3*bv.y; O[3][2] += a3*bv.z; O[3][3] += a3*bv.w;
        }
    }

    int b = bh >> 4, h = bh & 15;
    #pragma unroll
    for (int i = 0; i < 4; i++) {
        int tg = qr0 + ty*4 + i;
        float inv = 1.f / l[i];
        float4 o = make_float4(O[i][0]*inv, O[i][1]*inv, O[i][2]*inv, O[i][3]*inv);
        *(float4*)(g_ao + ((long)(b*TT + tg))*EE + h*64 + tx*4) = o;
    }
}

// ---------------- launch ---------------------------------------------------
extern "C" void kernel_launch(void* const* d_in, const int* in_sizes, int n_in,
                              void* d_out, int out_size)
{
    const float* x     = (const float*)d_in[0];
    const int*   tok   = (const int*)  d_in[1];
    const float* qwih  = (const float*)d_in[2];
    const float* qwhh  = (const float*)d_in[3];
    const float* qlinw = (const float*)d_in[4];
    const float* kwih  = (const float*)d_in[5];
    const float* kwhh  = (const float*)d_in[6];
    const float* klinw = (const float*)d_in[7];
    const float* vemb  = (const float*)d_in[8];
    const float* qlnw  = (const float*)d_in[9];
    const float* qlnb  = (const float*)d_in[10];
    const float* klnw  = (const float*)d_in[11];
    const float* klnb  = (const float*)d_in[12];
    const float* outw  = (const float*)d_in[13];
    const float* outb  = (const float*)d_in[14];
    float* out = (float*)d_out;

    static int attn_smem_set = 0;
    if (!attn_smem_set) {
        cudaFuncSetAttribute(attn2_kernel,
                             cudaFuncAttributeMaxDynamicSharedMemorySize, 65536);
        attn_smem_set = 1;
    }

    prep_kernel<<<NROW, 256>>>(x, tok, vemb, qwih, kwih);
    gru_kernel<<<4, 192>>>(qwhh, kwhh);
    sgemm_qk_kernel<<<dim3(EE/128, NROW/128, 2), 256>>>(x, qlinw, klinw);
    ln_stats_kernel<<<2*NROW, 256>>>();
    lnt_kernel<<<dim3(32, 32, 2), 256>>>(qlnw, qlnb, klnw, klnb);
    attn2_kernel<<<dim3(TT/64, BB*HN), 256, 65536>>>();
    sgemm_out_kernel<<<dim3(EE/128, NROW/128), 256>>>(outw, outb, out);
}

// round 3
// speedup vs baseline: 1.9867x; 1.4742x over previous
#include <cuda_runtime.h>
#include <math.h>

#define EE 1024
#define HN 16
#define HDIM 64
#define DI 64
#define BB 2
#define TT 2048
#define NROW (BB*TT)   // 4096
#define G3 192

// ---------------- scratch (static device memory) ---------------------------
__device__ float g_cat_q[NROW*EE];
__device__ float g_cat_k[NROW*EE];
__device__ float g_xw_q[NROW*G3];
__device__ float g_xw_k[NROW*G3];
__device__ float g_vh[BB*HN*TT*HDIM];   // [bh][t][d] (tf32-rounded)
__device__ float g_qpre[NROW*EE];
__device__ float g_kpre[NROW*EE];
__device__ float g_qh[BB*HN*TT*HDIM];   // [bh][t][d] (tf32-rounded)
__device__ float g_kh[BB*HN*TT*HDIM];   // [bh][t][d] (tf32-rounded)
__device__ float g_ao[NROW*EE];

__device__ __forceinline__ unsigned f2tf(float x) {
    unsigned r;
    asm("cvt.rna.tf32.f32 %0, %1;" : "=r"(r) : "f"(x));
    return r;
}
__device__ __forceinline__ float f2tff(float x) { return __uint_as_float(f2tf(x)); }

#define MMA_TF32(d, a, b0, b1) \
    asm volatile("mma.sync.aligned.m16n8k8.row.col.f32.tf32.tf32.f32 " \
        "{%0,%1,%2,%3},{%4,%5,%6,%7},{%8,%9},{%0,%1,%2,%3};" \
        : "+f"((d)[0]), "+f"((d)[1]), "+f"((d)[2]), "+f"((d)[3]) \
        : "r"((a)[0]), "r"((a)[1]), "r"((a)[2]), "r"((a)[3]), "r"(b0), "r"(b1))

// ---------------- kernel 1: fused prep -------------------------------------
__global__ void __launch_bounds__(256) prep_kernel(
    const float* __restrict__ x, const int* __restrict__ tok,
    const float* __restrict__ vemb,
    const float* __restrict__ qwih, const float* __restrict__ kwih)
{
    __shared__ float xsh[EE];
    __shared__ float xs[DI];
    int row = blockIdx.x;
    int tid = threadIdx.x;
    int b = row >> 11, t = row & (TT-1);

    ((float4*)xsh)[tid] = ((const float4*)(x + (long)row*EE))[tid];
    __syncthreads();

    int tk = tok[row];
    const float* ve = vemb + (long)tk*EE;
    for (int c = tid; c < EE; c += 256) {
        float xc = xsh[c];
        float s = xc / (1.f + __expf(-xc));
        float val = s * ve[c];
        int h = c >> 6, d = c & 63;
        g_vh[((long)(b*HN + h)*TT + t)*HDIM + d] = f2tff(val);
    }

    if (tid < DI) {
        float s = 0.f;
        #pragma unroll
        for (int i = 0; i < 16; i++) s += xsh[tid*16 + i];
        xs[tid] = s * (1.f/16.f);
    }
    __syncthreads();

    for (int idx = tid; idx < 2*G3; idx += 256) {
        int path = idx / G3, g = idx - path*G3;
        const float* w = (path ? kwih : qwih) + g*DI;
        float a0=0.f, a1=0.f, a2=0.f, a3=0.f;
        #pragma unroll
        for (int d = 0; d < DI; d += 4) {
            a0 += xs[d+0]*w[d+0];
            a1 += xs[d+1]*w[d+1];
            a2 += xs[d+2]*w[d+2];
            a3 += xs[d+3]*w[d+3];
        }
        float acc = (a0+a1)+(a2+a3);
        (path ? g_xw_k : g_xw_q)[(long)row*G3 + g] = acc;
    }

    for (int j = tid; j < EE - DI; j += 256) {
        int s0 = (j*16)/15;
        int e0 = ((j+1)*16 + 14)/15;
        float s = 0.f;
        for (int c = s0; c < e0; c++) s += xsh[c];
        s *= 1.f/(float)(e0 - s0);
        g_cat_q[(long)row*EE + DI + j] = s;
        g_cat_k[(long)row*EE + DI + j] = s;
    }
}

// ---------------- kernel 2: GRU recurrence ---------------------------------
__global__ void __launch_bounds__(192) gru_kernel(
    const float* __restrict__ qwhh, const float* __restrict__ kwhh)
{
    int path = blockIdx.x >> 1;
    int b = blockIdx.x & 1;
    int g = threadIdx.x;  // 0..191
    const float* whh = (path ? kwhh : qwhh) + g*DI;
    const float* xw  = (path ? g_xw_k : g_xw_q);
    float* cat = (path ? g_cat_k : g_cat_q);

    float4 w[16];
    #pragma unroll
    for (int i = 0; i < 16; i++) w[i] = ((const float4*)whh)[i];

    __shared__ float h_sh[DI];
    __shared__ float hw_sh[G3];
    __shared__ float xwn_sh[DI];
    if (g < DI) h_sh[g] = 0.f;
    __syncthreads();

    long base = (long)b*TT*G3 + g;
    float xwp = xw[base];
    for (int t = 0; t < TT; t++) {
        float xw_cur = xwp;
        if (t+1 < TT) xwp = xw[base + (long)(t+1)*G3];

        float acc[4] = {0.f, 0.f, 0.f, 0.f};
        #pragma unroll
        for (int i = 0; i < 16; i++) {
            float4 hv = ((const float4*)h_sh)[i];
            float4 wv = w[i];
            acc[i & 3] += hv.x*wv.x + hv.y*wv.y + hv.z*wv.z + hv.w*wv.w;
        }
        float hwraw = (acc[0]+acc[1]) + (acc[2]+acc[3]);
        hw_sh[g] = hwraw + ((g < 128) ? xw_cur : 0.f);
        if (g >= 128) xwn_sh[g - 128] = xw_cur;
        __syncthreads();
        if (g < DI) {
            float r = 1.f/(1.f + __expf(-hw_sh[g]));
            float z = 1.f/(1.f + __expf(-hw_sh[DI + g]));
            float n = __tanhf(xwn_sh[g] + r*hw_sh[128 + g]);
            float hn = (1.f - z)*n + z*h_sh[g];
            h_sh[g] = hn;
            cat[((long)b*TT + t)*EE + g] = hn;
        }
        __syncthreads();
    }
}

// ---------------- tf32 tensor-core GEMM: C = A @ W^T (+res)(+bias) ---------
// BM=BN=128, BK=16, 256 thr (8 warps: 2m x 4n), warp tile 64x32.
template<bool RES, bool BIAS>
__device__ __forceinline__ void tgemm_body(
    const float* __restrict__ A, const float* __restrict__ W,
    const float* __restrict__ res, const float* __restrict__ bias,
    float* __restrict__ C, int N, int K)
{
    __shared__ float As[2][128*20];
    __shared__ float Bs[2][128*20];
    int tid = threadIdx.x;
    int m0 = blockIdx.y * 128, n0 = blockIdx.x * 128;
    int wid = tid >> 5, lane = tid & 31;
    int g = lane >> 2, tig = lane & 3;
    int wm = (wid >> 2) * 64, wn = (wid & 3) * 32;
    int lrow = tid >> 2, lc = (tid & 3) * 4;

    const float* Ap = A + (long)(m0 + lrow)*K + lc;
    const float* Wp = W + (long)(n0 + lrow)*K + lc;

    float4 ra0 = *(const float4*)(Ap);
    float4 ra1 = *(const float4*)(Ap + (long)64*K);
    float4 rb0 = *(const float4*)(Wp);
    float4 rb1 = *(const float4*)(Wp + (long)64*K);

    float acc[4][4][4] = {};
    int buf = 0;
    const int NK = 64;  // K/16
    for (int kt = 0; kt < NK; kt++) {
        float* Asb = As[buf];
        float* Bsb = Bs[buf];
        *(float4*)(Asb + lrow*20 + lc) =
            make_float4(f2tff(ra0.x), f2tff(ra0.y), f2tff(ra0.z), f2tff(ra0.w));
        *(float4*)(Asb + (lrow+64)*20 + lc) =
            make_float4(f2tff(ra1.x), f2tff(ra1.y), f2tff(ra1.z), f2tff(ra1.w));
        *(float4*)(Bsb + lrow*20 + lc) =
            make_float4(f2tff(rb0.x), f2tff(rb0.y), f2tff(rb0.z), f2tff(rb0.w));
        *(float4*)(Bsb + (lrow+64)*20 + lc) =
            make_float4(f2tff(rb1.x), f2tff(rb1.y), f2tff(rb1.z), f2tff(rb1.w));
        __syncthreads();
        if (kt + 1 < NK) {
            int ko = (kt+1)*16;
            ra0 = *(const float4*)(Ap + ko);
            ra1 = *(const float4*)(Ap + (long)64*K + ko);
            rb0 = *(const float4*)(Wp + ko);
            rb1 = *(const float4*)(Wp + (long)64*K + ko);
        }
        #pragma unroll
        for (int kk = 0; kk < 16; kk += 8) {
            unsigned a[4][4], b[4][2];
            #pragma unroll
            for (int mt = 0; mt < 4; mt++) {
                int r = wm + mt*16 + g;
                a[mt][0] = __float_as_uint(Asb[r*20 + kk + tig]);
                a[mt][1] = __float_as_uint(Asb[(r+8)*20 + kk + tig]);
                a[mt][2] = __float_as_uint(Asb[r*20 + kk + tig + 4]);
                a[mt][3] = __float_as_uint(Asb[(r+8)*20 + kk + tig + 4]);
            }
            #pragma unroll
            for (int nt = 0; nt < 4; nt++) {
                int r = wn + nt*8 + g;
                b[nt][0] = __float_as_uint(Bsb[r*20 + kk + tig]);
                b[nt][1] = __float_as_uint(Bsb[r*20 + kk + tig + 4]);
            }
            #pragma unroll
            for (int mt = 0; mt < 4; mt++)
                #pragma unroll
                for (int nt = 0; nt < 4; nt++)
                    MMA_TF32(acc[mt][nt], a[mt], b[nt][0], b[nt][1]);
        }
        buf ^= 1;
    }

    #pragma unroll
    for (int mt = 0; mt < 4; mt++) {
        #pragma unroll
        for (int nt = 0; nt < 4; nt++) {
            long r0 = m0 + wm + mt*16 + g;
            long r1 = r0 + 8;
            long cb = n0 + wn + nt*8 + tig*2;
            float v0 = acc[mt][nt][0], v1 = acc[mt][nt][1];
            float v2 = acc[mt][nt][2], v3 = acc[mt][nt][3];
            if (RES) {
                float2 e0 = *(const float2*)(res + r0*N + cb);
                float2 e1 = *(const float2*)(res + r1*N + cb);
                v0 += e0.x; v1 += e0.y; v2 += e1.x; v3 += e1.y;
            }
            if (BIAS) {
                v0 += bias[cb]; v1 += bias[cb+1];
                v2 += bias[cb]; v3 += bias[cb+1];
            }
            *(float2*)(C + r0*N + cb) = make_float2(v0, v1);
            *(float2*)(C + r1*N + cb) = make_float2(v2, v3);
        }
    }
}

__global__ void __launch_bounds__(256) tgemm_qk_kernel(
    const float* __restrict__ x,
    const float* __restrict__ qW, const float* __restrict__ kW)
{
    int z = blockIdx.z;
    tgemm_body<true,false>(z ? g_cat_k : g_cat_q, z ? kW : qW, x, nullptr,
                           z ? g_kpre : g_qpre, EE, EE);
}

__global__ void __launch_bounds__(256) tgemm_out_kernel(
    const float* __restrict__ W, const float* __restrict__ bias,
    float* __restrict__ C)
{
    tgemm_body<false,true>(g_ao, W, nullptr, bias, C, EE, EE);
}

// ---------------- LayerNorm -> head-major [bh][t][d], tf32-rounded ---------
__global__ void __launch_bounds__(256) ln_kernel(
    const float* __restrict__ wq, const float* __restrict__ bq,
    const float* __restrict__ wk, const float* __restrict__ bk)
{
    int idx = blockIdx.x;
    int path = idx >> 12;
    int row = idx & 4095;
    const float* src = (path ? g_kpre : g_qpre) + (long)row*EE;
    const float* w = path ? wk : wq;
    const float* bb = path ? bk : bq;
    float* dst = path ? g_kh : g_qh;
    int tid = threadIdx.x;

    float4 v = ((const float4*)src)[tid];
    float s  = v.x + v.y + v.z + v.w;
    float sq = v.x*v.x + v.y*v.y + v.z*v.z + v.w*v.w;
    #pragma unroll
    for (int o = 16; o; o >>= 1) {
        s  += __shfl_xor_sync(0xffffffffu, s,  o);
        sq += __shfl_xor_sync(0xffffffffu, sq, o);
    }
    __shared__ float ss[8], sqs[8];
    __shared__ float mu_s, r_s;
    if ((tid & 31) == 0) { ss[tid >> 5] = s; sqs[tid >> 5] = sq; }
    __syncthreads();
    if (tid == 0) {
        float S = 0.f, SQ = 0.f;
        #pragma unroll
        for (int i = 0; i < 8; i++) { S += ss[i]; SQ += sqs[i]; }
        float mu = S * (1.f/EE);
        float var = SQ * (1.f/EE) - mu*mu;
        mu_s = mu;
        r_s = rsqrtf(var + 1e-5f);
    }
    __syncthreads();
    float mu = mu_s, r = r_s;
    int b = row >> 11, t = row & (TT-1);
    int c0 = tid * 4;
    int h = c0 >> 6, d = c0 & 63;
    float4 o;
    o.x = f2tff((v.x - mu)*r*w[c0+0] + bb[c0+0]);
    o.y = f2tff((v.y - mu)*r*w[c0+1] + bb[c0+1]);
    o.z = f2tff((v.z - mu)*r*w[c0+2] + bb[c0+2]);
    o.w = f2tff((v.w - mu)*r*w[c0+3] + bb[c0+3]);
    *(float4*)&dst[((long)(b*HN + h)*TT + t)*HDIM + d] = o;
}

// ---------------- tf32 tensor-core flash attention -------------------------
// Br=128, Bc=32, 256 thr = 8 warps; warp w owns q-rows [w*16, w*16+16).
__global__ void __launch_bounds__(256) attn3_kernel()
{
    __shared__ float smem_buf[9088];
    float* Qs = smem_buf;            // [128][68] (phase 0 only)
    float* Ks = smem_buf;            // [32][68]
    float* Vs = smem_buf + 2176;     // [32][72]
    float* Ps = smem_buf + 4480;     // [128][36]

    int bh = blockIdx.y;
    int qblk = (int)gridDim.x - 1 - (int)blockIdx.x;  // longest first
    int qr0 = qblk * 128;
    int tid = threadIdx.x;
    int wid = tid >> 5, lane = tid & 31;
    int g = lane >> 2, tig = lane & 3;
    int r0 = wid * 16;

    const float* qbase = g_qh + (long)bh*TT*HDIM;
    const float* kbase = g_kh + (long)bh*TT*HDIM;
    const float* vbase = g_vh + (long)bh*TT*HDIM;

    // ---- load Q tile, extract per-warp fragments to registers ----
    #pragma unroll
    for (int i = 0; i < 8; i++) {
        int f = tid + i*256;
        int rr = f >> 4, c4 = (f & 15) * 4;
        *(float4*)(Qs + rr*68 + c4) =
            *(const float4*)(qbase + (long)(qr0 + rr)*HDIM + c4);
    }
    __syncthreads();
    unsigned qf[8][4];
    #pragma unroll
    for (int k8 = 0; k8 < 8; k8++) {
        int kb = k8*8;
        qf[k8][0] = __float_as_uint(Qs[(r0+g)*68 + kb + tig]);
        qf[k8][1] = __float_as_uint(Qs[(r0+g+8)*68 + kb + tig]);
        qf[k8][2] = __float_as_uint(Qs[(r0+g)*68 + kb + tig + 4]);
        qf[k8][3] = __float_as_uint(Qs[(r0+g+8)*68 + kb + tig + 4]);
    }

    float o[8][4] = {};
    float m0 = -1e30f, m1 = -1e30f, l0 = 0.f, l1 = 0.f;
    int rowA = qr0 + r0 + g;
    int rowB = rowA + 8;
    int wrow_lo = qr0 + r0;          // warp's first row
    int wrow_hi = wrow_lo + 15;      // warp's last row

    int nchunk = 4 * (qblk + 1);
    for (int c = 0; c < nchunk; c++) {
        int s0 = c * 32;
        __syncthreads();   // protect Ks/Vs (and Qs on first iter)
        #pragma unroll
        for (int i = 0; i < 2; i++) {
            int f = tid + i*256;
            int rr = f >> 4, c4 = (f & 15) * 4;
            *(float4*)(Ks + rr*68 + c4) =
                *(const float4*)(kbase + (long)(s0 + rr)*HDIM + c4);
            *(float4*)(Vs + rr*72 + c4) =
                *(const float4*)(vbase + (long)(s0 + rr)*HDIM + c4);
        }
        __syncthreads();

        if (s0 > wrow_hi) continue;   // warp tile fully masked

        // ---- S = Q K^T ----
        float sacc[4][4] = {};
        #pragma unroll
        for (int k8 = 0; k8 < 8; k8++) {
            int kb = k8*8;
            #pragma unroll
            for (int nt = 0; nt < 4; nt++) {
                int rr = nt*8 + g;
                unsigned b0 = __float_as_uint(Ks[rr*68 + kb + tig]);
                unsigned b1 = __float_as_uint(Ks[rr*68 + kb + tig + 4]);
                MMA_TF32(sacc[nt], qf[k8], b0, b1);
            }
        }

        // ---- scale + causal mask ----
        bool needmask = (s0 + 31 > wrow_lo);
        #pragma unroll
        for (int nt = 0; nt < 4; nt++) {
            int col0 = s0 + nt*8 + tig*2;
            float v0 = sacc[nt][0]*0.25f, v1 = sacc[nt][1]*0.25f;
            float v2 = sacc[nt][2]*0.25f, v3 = sacc[nt][3]*0.25f;
            if (needmask) {
                if (col0     > rowA) v0 = -1e30f;
                if (col0 + 1 > rowA) v1 = -1e30f;
                if (col0     > rowB) v2 = -1e30f;
                if (col0 + 1 > rowB) v3 = -1e30f;
            }
            sacc[nt][0] = v0; sacc[nt][1] = v1; sacc[nt][2] = v2; sacc[nt][3] = v3;
        }

        // ---- online softmax (rows warp-local; quad shuffles) ----
        float rm0 = -1e30f, rm1 = -1e30f;
        #pragma unroll
        for (int nt = 0; nt < 4; nt++) {
            rm0 = fmaxf(rm0, fmaxf(sacc[nt][0], sacc[nt][1]));
            rm1 = fmaxf(rm1, fmaxf(sacc[nt][2], sacc[nt][3]));
        }
        rm0 = fmaxf(rm0, __shfl_xor_sync(0xffffffffu, rm0, 1));
        rm0 = fmaxf(rm0, __shfl_xor_sync(0xffffffffu, rm0, 2));
        rm1 = fmaxf(rm1, __shfl_xor_sync(0xffffffffu, rm1, 1));
        rm1 = fmaxf(rm1, __shfl_xor_sync(0xffffffffu, rm1, 2));
        float mn0 = fmaxf(m0, rm0), mn1 = fmaxf(m1, rm1);
        float c0 = __expf(m0 - mn0), c1 = __expf(m1 - mn1);
        m0 = mn0; m1 = mn1;

        float ps0 = 0.f, ps1 = 0.f;
        #pragma unroll
        for (int nt = 0; nt < 4; nt++) {
            float p0 = __expf(sacc[nt][0] - mn0);
            float p1 = __expf(sacc[nt][1] - mn0);
            float p2 = __expf(sacc[nt][2] - mn1);
            float p3 = __expf(sacc[nt][3] - mn1);
            ps0 += p0 + p1; ps1 += p2 + p3;
            int cb = nt*8 + tig*2;
            *(float2*)(Ps + (r0+g)*36 + cb)   = make_float2(f2tff(p0), f2tff(p1));
            *(float2*)(Ps + (r0+g+8)*36 + cb) = make_float2(f2tff(p2), f2tff(p3));
        }
        ps0 += __shfl_xor_sync(0xffffffffu, ps0, 1);
        ps0 += __shfl_xor_sync(0xffffffffu, ps0, 2);
        ps1 += __shfl_xor_sync(0xffffffffu, ps1, 1);
        ps1 += __shfl_xor_sync(0xffffffffu, ps1, 2);
        l0 = l0*c0 + ps0;
        l1 = l1*c1 + ps1;

        #pragma unroll
        for (int nt = 0; nt < 8; nt++) {
            o[nt][0] *= c0; o[nt][1] *= c0;
            o[nt][2] *= c1; o[nt][3] *= c1;
        }
        __syncwarp();   // Ps visibility across lanes of this warp

        // ---- O += P V ----
        #pragma unroll
        for (int k8 = 0; k8 < 4; k8++) {
            int kb = k8*8;
            unsigned a[4];
            a[0] = __float_as_uint(Ps[(r0+g)*36 + kb + tig]);
            a[1] = __float_as_uint(Ps[(r0+g+8)*36 + kb + tig]);
            a[2] = __float_as_uint(Ps[(r0+g)*36 + kb + tig + 4]);
            a[3] = __float_as_uint(Ps[(r0+g+8)*36 + kb + tig + 4]);
            #pragma unroll
            for (int nt = 0; nt < 8; nt++) {
                unsigned b0 = __float_as_uint(Vs[(kb+tig)*72 + nt*8 + g]);
                unsigned b1 = __float_as_uint(Vs[(kb+tig+4)*72 + nt*8 + g]);
                MMA_TF32(o[nt], a, b0, b1);
            }
        }
    }

    // ---- write O ----
    int b = bh >> 4, h = bh & 15;
    float i0 = 1.f / l0, i1 = 1.f / l1;
    #pragma unroll
    for (int nt = 0; nt < 8; nt++) {
        int cb = h*64 + nt*8 + tig*2;
        *(float2*)(g_ao + ((long)(b*TT + rowA))*EE + cb) =
            make_float2(o[nt][0]*i0, o[nt][1]*i0);
        *(float2*)(g_ao + ((long)(b*TT + rowB))*EE + cb) =
            make_float2(o[nt][2]*i1, o[nt][3]*i1);
    }
}

// ---------------- launch ---------------------------------------------------
extern "C" void kernel_launch(void* const* d_in, const int* in_sizes, int n_in,
                              void* d_out, int out_size)
{
    const float* x     = (const float*)d_in[0];
    const int*   tok   = (const int*)  d_in[1];
    const float* qwih  = (const float*)d_in[2];
    const float* qwhh  = (const float*)d_in[3];
    const float* qlinw = (const float*)d_in[4];
    const float* kwih  = (const float*)d_in[5];
    const float* kwhh  = (const float*)d_in[6];
    const float* klinw = (const float*)d_in[7];
    const float* vemb  = (const float*)d_in[8];
    const float* qlnw  = (const float*)d_in[9];
    const float* qlnb  = (const float*)d_in[10];
    const float* klnw  = (const float*)d_in[11];
    const float* klnb  = (const float*)d_in[12];
    const float* outw  = (const float*)d_in[13];
    const float* outb  = (const float*)d_in[14];
    float* out = (float*)d_out;

    prep_kernel<<<NROW, 256>>>(x, tok, vemb, qwih, kwih);
    gru_kernel<<<4, 192>>>(qwhh, kwhh);
    tgemm_qk_kernel<<<dim3(EE/128, NROW/128, 2), 256>>>(x, qlinw, klinw);
    ln_kernel<<<2*NROW, 256>>>(qlnw, qlnb, klnw, klnb);
    attn3_kernel<<<dim3(TT/128, BB*HN), 256>>>();
    tgemm_out_kernel<<<dim3(EE/128, NROW/128), 256>>>(outw, outb, out);
}

// round 4
// speedup vs baseline: 1.9885x; 1.0009x over previous
#include <cuda_runtime.h>
#include <math.h>

#define EE 1024
#define HN 16
#define HDIM 64
#define DI 64
#define BB 2
#define TT 2048
#define NROW (BB*TT)   // 4096
#define G3 192
#define KP 960         // proj K

// ---------------- scratch (static device memory) ---------------------------
__device__ float g_proj[NROW*KP];       // tf32-rounded, shared by q/k
__device__ float g_xw_q[NROW*G3];
__device__ float g_xw_k[NROW*G3];
__device__ float g_pos_q[NROW*DI];
__device__ float g_pos_k[NROW*DI];
__device__ float g_vh[BB*HN*TT*HDIM];   // [bh][t][d] tf32
__device__ float g_qpre[NROW*EE];
__device__ float g_kpre[NROW*EE];
__device__ float g_qh[BB*HN*TT*HDIM];   // tf32
__device__ float g_kh[BB*HN*TT*HDIM];   // tf32
__device__ float g_ao[NROW*EE];         // tf32
__device__ float g_wq[EE*EE];           // tf32 weights
__device__ float g_wk[EE*EE];
__device__ float g_wo[EE*EE];

__device__ __forceinline__ unsigned f2tf(float x) {
    unsigned r;
    asm("cvt.rna.tf32.f32 %0, %1;" : "=r"(r) : "f"(x));
    return r;
}
__device__ __forceinline__ float f2tff(float x) { return __uint_as_float(f2tf(x)); }

#define MMA_TF32(d, a, b0, b1) \
    asm volatile("mma.sync.aligned.m16n8k8.row.col.f32.tf32.tf32.f32 " \
        "{%0,%1,%2,%3},{%4,%5,%6,%7},{%8,%9},{%0,%1,%2,%3};" \
        : "+f"((d)[0]), "+f"((d)[1]), "+f"((d)[2]), "+f"((d)[3]) \
        : "r"((a)[0]), "r"((a)[1]), "r"((a)[2]), "r"((a)[3]), "r"(b0), "r"(b1))

#define CPA16(dst_u32, src) \
    asm volatile("cp.async.cg.shared.global [%0], [%1], 16;" :: "r"(dst_u32), "l"(src))
#define CPCOMMIT() asm volatile("cp.async.commit_group;")
#define CPWAIT(n)  asm volatile("cp.async.wait_group %0;" :: "n"(n))

// ---------------- weight convert to tf32 -----------------------------------
__global__ void __launch_bounds__(256) wconv_kernel(
    const float* __restrict__ qw, const float* __restrict__ kw,
    const float* __restrict__ ow)
{
    const float* src = blockIdx.y == 0 ? qw : (blockIdx.y == 1 ? kw : ow);
    float* dst = blockIdx.y == 0 ? g_wq : (blockIdx.y == 1 ? g_wk : g_wo);
    long i = ((long)blockIdx.x*256 + threadIdx.x)*4;
    float4 v = *(const float4*)(src + i);
    *(float4*)(dst + i) = make_float4(f2tff(v.x), f2tff(v.y), f2tff(v.z), f2tff(v.w));
}

// ---------------- kernel 1: fused prep -------------------------------------
__global__ void __launch_bounds__(256) prep_kernel(
    const float* __restrict__ x, const int* __restrict__ tok,
    const float* __restrict__ vemb,
    const float* __restrict__ qwih, const float* __restrict__ kwih)
{
    __shared__ float xsh[EE];
    __shared__ float xs[DI];
    int row = blockIdx.x;
    int tid = threadIdx.x;
    int b = row >> 11, t = row & (TT-1);

    ((float4*)xsh)[tid] = ((const float4*)(x + (long)row*EE))[tid];
    __syncthreads();

    int tk = tok[row];
    const float* ve = vemb + (long)tk*EE;
    for (int c = tid; c < EE; c += 256) {
        float xc = xsh[c];
        float s = xc / (1.f + __expf(-xc));
        float val = s * ve[c];
        int h = c >> 6, d = c & 63;
        g_vh[((long)(b*HN + h)*TT + t)*HDIM + d] = f2tff(val);
    }

    if (tid < DI) {
        float s = 0.f;
        #pragma unroll
        for (int i = 0; i < 16; i++) s += xsh[tid*16 + i];
        xs[tid] = s * (1.f/16.f);
    }
    __syncthreads();

    for (int idx = tid; idx < 2*G3; idx += 256) {
        int path = idx / G3, g = idx - path*G3;
        const float* w = (path ? kwih : qwih) + g*DI;
        float a0=0.f, a1=0.f, a2=0.f, a3=0.f;
        #pragma unroll
        for (int d = 0; d < DI; d += 4) {
            a0 += xs[d+0]*w[d+0];
            a1 += xs[d+1]*w[d+1];
            a2 += xs[d+2]*w[d+2];
            a3 += xs[d+3]*w[d+3];
        }
        float acc = (a0+a1)+(a2+a3);
        (path ? g_xw_k : g_xw_q)[(long)row*G3 + g] = acc;
    }

    // proj (pool 1024 -> 960), tf32-rounded, written once (path-independent)
    for (int j = tid; j < KP; j += 256) {
        int s0 = (j*16)/15;
        int e0 = ((j+1)*16 + 14)/15;
        float s = 0.f;
        for (int c = s0; c < e0; c++) s += xsh[c];
        s *= 1.f/(float)(e0 - s0);
        g_proj[(long)row*KP + j] = f2tff(s);
    }
}

// ---------------- kernel 2: GRU recurrence ---------------------------------
__global__ void __launch_bounds__(192) gru_kernel(
    const float* __restrict__ qwhh, const float* __restrict__ kwhh)
{
    int path = blockIdx.x >> 1;
    int b = blockIdx.x & 1;
    int g = threadIdx.x;  // 0..191
    const float* whh = (path ? kwhh : qwhh) + g*DI;
    const float* xw  = (path ? g_xw_k : g_xw_q);
    float* pos = (path ? g_pos_k : g_pos_q);

    float4 w[16];
    #pragma unroll
    for (int i = 0; i < 16; i++) w[i] = ((const float4*)whh)[i];

    __shared__ float h_sh[DI];
    __shared__ float hw_sh[G3];
    __shared__ float xwn_sh[DI];
    if (g < DI) h_sh[g] = 0.f;
    __syncthreads();

    long base = (long)b*TT*G3 + g;
    float xwp = xw[base];
    for (int t = 0; t < TT; t++) {
        float xw_cur = xwp;
        if (t+1 < TT) xwp = xw[base + (long)(t+1)*G3];

        float acc[4] = {0.f, 0.f, 0.f, 0.f};
        #pragma unroll
        for (int i = 0; i < 16; i++) {
            float4 hv = ((const float4*)h_sh)[i];
            float4 wv = w[i];
            acc[i & 3] += hv.x*wv.x + hv.y*wv.y + hv.z*wv.z + hv.w*wv.w;
        }
        float hwraw = (acc[0]+acc[1]) + (acc[2]+acc[3]);
        hw_sh[g] = hwraw + ((g < 128) ? xw_cur : 0.f);
        if (g >= 128) xwn_sh[g - 128] = xw_cur;
        __syncthreads();
        if (g < DI) {
            float r = 1.f/(1.f + __expf(-hw_sh[g]));
            float z = 1.f/(1.f + __expf(-hw_sh[DI + g]));
            float n = __tanhf(xwn_sh[g] + r*hw_sh[128 + g]);
            float hn = (1.f - z)*n + z*h_sh[g];
            h_sh[g] = hn;
            pos[((long)b*TT + t)*DI + g] = hn;
        }
        __syncthreads();
    }
}

// ---------------- tf32 tensor-core GEMM: C = A @ W^T (+res)(+bias) ---------
// BM=BN=128, BK=16, 256 thr (8 warps: 2m x 4n), warp tile 64x32.
// Inputs pre-rounded to tf32; raw copies into smem.
template<bool RES, bool BIAS>
__device__ __forceinline__ void tgemm_body(
    const float* __restrict__ A, int lda,
    const float* __restrict__ W, int ldw,
    const float* __restrict__ res, const float* __restrict__ bias,
    float* __restrict__ C, int N, int NK)
{
    __shared__ float As[2][128*20];
    __shared__ float Bs[2][128*20];
    int tid = threadIdx.x;
    int m0 = blockIdx.y * 128, n0 = blockIdx.x * 128;
    int wid = tid >> 5, lane = tid & 31;
    int g = lane >> 2, tig = lane & 3;
    int wm = (wid >> 2) * 64, wn = (wid & 3) * 32;
    int lrow = tid >> 2, lc = (tid & 3) * 4;

    const float* Ap = A + (long)(m0 + lrow)*lda + lc;
    const float* Wp = W + (long)(n0 + lrow)*ldw + lc;

    float4 ra0 = *(const float4*)(Ap);
    float4 ra1 = *(const float4*)(Ap + (long)64*lda);
    float4 rb0 = *(const float4*)(Wp);
    float4 rb1 = *(const float4*)(Wp + (long)64*ldw);

    float acc[4][4][4] = {};
    int buf = 0;
    for (int kt = 0; kt < NK; kt++) {
        float* Asb = As[buf];
        float* Bsb = Bs[buf];
        *(float4*)(Asb + lrow*20 + lc) = ra0;
        *(float4*)(Asb + (lrow+64)*20 + lc) = ra1;
        *(float4*)(Bsb + lrow*20 + lc) = rb0;
        *(float4*)(Bsb + (lrow+64)*20 + lc) = rb1;
        __syncthreads();
        if (kt + 1 < NK) {
            int ko = (kt+1)*16;
            ra0 = *(const float4*)(Ap + ko);
            ra1 = *(const float4*)(Ap + (long)64*lda + ko);
            rb0 = *(const float4*)(Wp + ko);
            rb1 = *(const float4*)(Wp + (long)64*ldw + ko);
        }
        #pragma unroll
        for (int kk = 0; kk < 16; kk += 8) {
            unsigned a[4][4], b[4][2];
            #pragma unroll
            for (int mt = 0; mt < 4; mt++) {
                int r = wm + mt*16 + g;
                a[mt][0] = __float_as_uint(Asb[r*20 + kk + tig]);
                a[mt][1] = __float_as_uint(Asb[(r+8)*20 + kk + tig]);
                a[mt][2] = __float_as_uint(Asb[r*20 + kk + tig + 4]);
                a[mt][3] = __float_as_uint(Asb[(r+8)*20 + kk + tig + 4]);
            }
            #pragma unroll
            for (int nt = 0; nt < 4; nt++) {
                int r = wn + nt*8 + g;
                b[nt][0] = __float_as_uint(Bsb[r*20 + kk + tig]);
                b[nt][1] = __float_as_uint(Bsb[r*20 + kk + tig + 4]);
            }
            #pragma unroll
            for (int mt = 0; mt < 4; mt++)
                #pragma unroll
                for (int nt = 0; nt < 4; nt++)
                    MMA_TF32(acc[mt][nt], a[mt], b[nt][0], b[nt][1]);
        }
        buf ^= 1;
    }

    #pragma unroll
    for (int mt = 0; mt < 4; mt++) {
        #pragma unroll
        for (int nt = 0; nt < 4; nt++) {
            long r0 = m0 + wm + mt*16 + g;
            long r1 = r0 + 8;
            long cb = n0 + wn + nt*8 + tig*2;
            float v0 = acc[mt][nt][0], v1 = acc[mt][nt][1];
            float v2 = acc[mt][nt][2], v3 = acc[mt][nt][3];
            if (RES) {
                float2 e0 = *(const float2*)(res + r0*N + cb);
                float2 e1 = *(const float2*)(res + r1*N + cb);
                v0 += e0.x; v1 += e0.y; v2 += e1.x; v3 += e1.y;
            }
            if (BIAS) {
                v0 += bias[cb]; v1 += bias[cb+1];
                v2 += bias[cb]; v3 += bias[cb+1];
            }
            *(float2*)(C + r0*N + cb) = make_float2(v0, v1);
            *(float2*)(C + r1*N + cb) = make_float2(v2, v3);
        }
    }
}

// big q/k projection: K=960 (proj part only), + residual x
__global__ void __launch_bounds__(256) tgemm_qk_kernel(const float* __restrict__ x)
{
    int z = blockIdx.z;
    tgemm_body<true,false>(g_proj, KP, (z ? g_wk : g_wq) + DI, EE, x, nullptr,
                           z ? g_kpre : g_qpre, EE, KP/16);
}

__global__ void __launch_bounds__(256) tgemm_out_kernel(
    const float* __restrict__ bias, float* __restrict__ C)
{
    tgemm_body<false,true>(g_ao, EE, g_wo, EE, nullptr, bias, C, EE, EE/16);
}

// ---------------- pos small GEMM: C += pos @ Wpos^T (K=64, fp32) -----------
// block: 32 rows x 128 cols; grid (8, 128, 2)
__global__ void __launch_bounds__(256) posgemm_kernel(
    const float* __restrict__ qw, const float* __restrict__ kw)
{
    int path = blockIdx.z;
    const float* pos = path ? g_pos_k : g_pos_q;
    const float* W = path ? kw : qw;         // [n][EE], cols 0..63
    float* C = path ? g_kpre : g_qpre;
    __shared__ float Wt[64][132];            // transposed [k][n]
    __shared__ float Ps_[32][68];
    int n0 = blockIdx.x * 128;
    int m0 = blockIdx.y * 32;
    int tid = threadIdx.x;

    // load W tile transposed: 128 rows x 64 k
    for (int i = tid; i < 128*16; i += 256) {
        int r = i >> 4, c4 = (i & 15)*4;
        float4 v = *(const float4*)(W + (long)(n0 + r)*EE + c4);
        Wt[c4+0][r] = v.x; Wt[c4+1][r] = v.y; Wt[c4+2][r] = v.z; Wt[c4+3][r] = v.w;
    }
    for (int i = tid; i < 32*16; i += 256) {
        int r = i >> 4, c4 = (i & 15)*4;
        *(float4*)&Ps_[r][c4] = *(const float4*)(pos + (long)(m0 + r)*DI + c4);
    }
    __syncthreads();

    int tx = tid & 15, ty = tid >> 4;
    int r0 = ty*2, c0 = tx*8;
    float acc[2][8] = {};
    #pragma unroll
    for (int k = 0; k < 64; k++) {
        float p0 = Ps_[r0][k], p1 = Ps_[r0+1][k];
        float4 w0 = *(float4*)&Wt[k][c0];
        float4 w1 = *(float4*)&Wt[k][c0+4];
        acc[0][0] += p0*w0.x; acc[0][1] += p0*w0.y; acc[0][2] += p0*w0.z; acc[0][3] += p0*w0.w;
        acc[0][4] += p0*w1.x; acc[0][5] += p0*w1.y; acc[0][6] += p0*w1.z; acc[0][7] += p0*w1.w;
        acc[1][0] += p1*w0.x; acc[1][1] += p1*w0.y; acc[1][2] += p1*w0.z; acc[1][3] += p1*w0.w;
        acc[1][4] += p1*w1.x; acc[1][5] += p1*w1.y; acc[1][6] += p1*w1.z; acc[1][7] += p1*w1.w;
    }
    #pragma unroll
    for (int i = 0; i < 2; i++) {
        long m = m0 + r0 + i;
        #pragma unroll
        for (int j = 0; j < 8; j += 4) {
            float4 old = *(float4*)(C + m*EE + n0 + c0 + j);
            old.x += acc[i][j]; old.y += acc[i][j+1];
            old.z += acc[i][j+2]; old.w += acc[i][j+3];
            *(float4*)(C + m*EE + n0 + c0 + j) = old;
        }
    }
}

// ---------------- LayerNorm -> head-major [bh][t][d], tf32-rounded ---------
__global__ void __launch_bounds__(256) ln_kernel(
    const float* __restrict__ wq, const float* __restrict__ bq,
    const float* __restrict__ wk, const float* __restrict__ bk)
{
    int idx = blockIdx.x;
    int path = idx >> 12;
    int row = idx & 4095;
    const float* src = (path ? g_kpre : g_qpre) + (long)row*EE;
    const float* w = path ? wk : wq;
    const float* bb = path ? bk : bq;
    float* dst = path ? g_kh : g_qh;
    int tid = threadIdx.x;

    float4 v = ((const float4*)src)[tid];
    float s  = v.x + v.y + v.z + v.w;
    float sq = v.x*v.x + v.y*v.y + v.z*v.z + v.w*v.w;
    #pragma unroll
    for (int o = 16; o; o >>= 1) {
        s  += __shfl_xor_sync(0xffffffffu, s,  o);
        sq += __shfl_xor_sync(0xffffffffu, sq, o);
    }
    __shared__ float ss[8], sqs[8];
    __shared__ float mu_s, r_s;
    if ((tid & 31) == 0) { ss[tid >> 5] = s; sqs[tid >> 5] = sq; }
    __syncthreads();
    if (tid == 0) {
        float S = 0.f, SQ = 0.f;
        #pragma unroll
        for (int i = 0; i < 8; i++) { S += ss[i]; SQ += sqs[i]; }
        float mu = S * (1.f/EE);
        float var = SQ * (1.f/EE) - mu*mu;
        mu_s = mu;
        r_s = rsqrtf(var + 1e-5f);
    }
    __syncthreads();
    float mu = mu_s, r = r_s;
    int b = row >> 11, t = row & (TT-1);
    int c0 = tid * 4;
    int h = c0 >> 6, d = c0 & 63;
    float4 o;
    o.x = f2tff((v.x - mu)*r*w[c0+0] + bb[c0+0]);
    o.y = f2tff((v.y - mu)*r*w[c0+1] + bb[c0+1]);
    o.z = f2tff((v.z - mu)*r*w[c0+2] + bb[c0+2]);
    o.w = f2tff((v.w - mu)*r*w[c0+3] + bb[c0+3]);
    *(float4*)&dst[((long)(b*HN + h)*TT + t)*HDIM + d] = o;
}

// ---------------- tf32 flash attention, cp.async double-buffered -----------
// Br=128, Bc=32, 256 thr = 8 warps; warp w owns q-rows [w*16, w*16+16).
#define KS_STR 68
#define VS_STR 72
#define KV_BUF 4480            // 32*68 + 32*72
#define PS_OFF 8960
#define ATT_SMEM ((8960 + 128*36)*4)

__device__ __forceinline__ void attn_issue(
    float* sm, int buf, int s0, int tid,
    const float* kbase, const float* vbase)
{
    float* Kb = sm + buf*KV_BUF;
    float* Vb = Kb + 32*KS_STR;
    #pragma unroll
    for (int i = 0; i < 2; i++) {
        int f = tid + i*256;
        int rr = f >> 4, c4 = (f & 15) * 4;
        unsigned kd = (unsigned)__cvta_generic_to_shared(Kb + rr*KS_STR + c4);
        unsigned vd = (unsigned)__cvta_generic_to_shared(Vb + rr*VS_STR + c4);
        CPA16(kd, kbase + (long)(s0 + rr)*HDIM + c4);
        CPA16(vd, vbase + (long)(s0 + rr)*HDIM + c4);
    }
}

__global__ void __launch_bounds__(256) attn3_kernel()
{
    extern __shared__ float sm[];
    float* Qs = sm;              // [128][68] (pre-loop only)
    float* Ps = sm + PS_OFF;     // [128][36]

    int bh = blockIdx.y;
    int qblk = (int)gridDim.x - 1 - (int)blockIdx.x;  // longest first
    int qr0 = qblk * 128;
    int tid = threadIdx.x;
    int wid = tid >> 5, lane = tid & 31;
    int g = lane >> 2, tig = lane & 3;
    int r0 = wid * 16;

    const float* qbase = g_qh + (long)bh*TT*HDIM;
    const float* kbase = g_kh + (long)bh*TT*HDIM;
    const float* vbase = g_vh + (long)bh*TT*HDIM;

    // ---- load Q tile, extract per-warp fragments ----
    #pragma unroll
    for (int i = 0; i < 8; i++) {
        int f = tid + i*256;
        int rr = f >> 4, c4 = (f & 15) * 4;
        *(float4*)(Qs + rr*KS_STR + c4) =
            *(const float4*)(qbase + (long)(qr0 + rr)*HDIM + c4);
    }
    __syncthreads();
    unsigned qf[8][4];
    #pragma unroll
    for (int k8 = 0; k8 < 8; k8++) {
        int kb = k8*8;
        qf[k8][0] = __float_as_uint(Qs[(r0+g)*KS_STR + kb + tig]);
        qf[k8][1] = __float_as_uint(Qs[(r0+g+8)*KS_STR + kb + tig]);
        qf[k8][2] = __float_as_uint(Qs[(r0+g)*KS_STR + kb + tig + 4]);
        qf[k8][3] = __float_as_uint(Qs[(r0+g+8)*KS_STR + kb + tig + 4]);
    }
    __syncthreads();   // everyone done with Qs; smem reused for K/V

    float o[8][4] = {};
    float m0 = -1e30f, m1 = -1e30f, l0 = 0.f, l1 = 0.f;
    int rowA = qr0 + r0 + g;
    int rowB = rowA + 8;
    int wrow_lo = qr0 + r0;
    int wrow_hi = wrow_lo + 15;

    int nchunk = 4 * (qblk + 1);
    attn_issue(sm, 0, 0, tid, kbase, vbase);
    CPCOMMIT();

    for (int c = 0; c < nchunk; c++) {
        int s0 = c * 32;
        if (c + 1 < nchunk) {
            attn_issue(sm, (c+1) & 1, s0 + 32, tid, kbase, vbase);
            CPCOMMIT();
            CPWAIT(1);
        } else {
            CPWAIT(0);
        }
        __syncthreads();   // chunk c visible to all

        if (s0 <= wrow_hi) {
            float* Ks = sm + (c & 1)*KV_BUF;
            float* Vs = Ks + 32*KS_STR;

            // ---- S = Q K^T ----
            float sacc[4][4] = {};
            #pragma unroll
            for (int k8 = 0; k8 < 8; k8++) {
                int kb = k8*8;
                #pragma unroll
                for (int nt = 0; nt < 4; nt++) {
                    int rr = nt*8 + g;
                    unsigned b0 = __float_as_uint(Ks[rr*KS_STR + kb + tig]);
                    unsigned b1 = __float_as_uint(Ks[rr*KS_STR + kb + tig + 4]);
                    MMA_TF32(sacc[nt], qf[k8], b0, b1);
                }
            }

            // ---- scale + causal mask ----
            bool needmask = (s0 + 31 > wrow_lo);
            #pragma unroll
            for (int nt = 0; nt < 4; nt++) {
                int col0 = s0 + nt*8 + tig*2;
                float v0 = sacc[nt][0]*0.25f, v1 = sacc[nt][1]*0.25f;
                float v2 = sacc[nt][2]*0.25f, v3 = sacc[nt][3]*0.25f;
                if (needmask) {
                    if (col0     > rowA) v0 = -1e30f;
                    if (col0 + 1 > rowA) v1 = -1e30f;
                    if (col0     > rowB) v2 = -1e30f;
                    if (col0 + 1 > rowB) v3 = -1e30f;
                }
                sacc[nt][0] = v0; sacc[nt][1] = v1; sacc[nt][2] = v2; sacc[nt][3] = v3;
            }

            // ---- online softmax ----
            float rm0 = -1e30f, rm1 = -1e30f;
            #pragma unroll
            for (int nt = 0; nt < 4; nt++) {
                rm0 = fmaxf(rm0, fmaxf(sacc[nt][0], sacc[nt][1]));
                rm1 = fmaxf(rm1, fmaxf(sacc[nt][2], sacc[nt][3]));
            }
            rm0 = fmaxf(rm0, __shfl_xor_sync(0xffffffffu, rm0, 1));
            rm0 = fmaxf(rm0, __shfl_xor_sync(0xffffffffu, rm0, 2));
            rm1 = fmaxf(rm1, __shfl_xor_sync(0xffffffffu, rm1, 1));
            rm1 = fmaxf(rm1, __shfl_xor_sync(0xffffffffu, rm1, 2));
            float mn0 = fmaxf(m0, rm0), mn1 = fmaxf(m1, rm1);
            float c0f = __expf(m0 - mn0), c1f = __expf(m1 - mn1);
            m0 = mn0; m1 = mn1;

            float ps0 = 0.f, ps1 = 0.f;
            #pragma unroll
            for (int nt = 0; nt < 4; nt++) {
                float p0 = __expf(sacc[nt][0] - mn0);
                float p1 = __expf(sacc[nt][1] - mn0);
                float p2 = __expf(sacc[nt][2] - mn1);
                float p3 = __expf(sacc[nt][3] - mn1);
                ps0 += p0 + p1; ps1 += p2 + p3;
                int cb = nt*8 + tig*2;
                *(float2*)(Ps + (r0+g)*36 + cb)   = make_float2(f2tff(p0), f2tff(p1));
                *(float2*)(Ps + (r0+g+8)*36 + cb) = make_float2(f2tff(p2), f2tff(p3));
            }
            ps0 += __shfl_xor_sync(0xffffffffu, ps0, 1);
            ps0 += __shfl_xor_sync(0xffffffffu, ps0, 2);
            ps1 += __shfl_xor_sync(0xffffffffu, ps1, 1);
            ps1 += __shfl_xor_sync(0xffffffffu, ps1, 2);
            l0 = l0*c0f + ps0;
            l1 = l1*c1f + ps1;

            #pragma unroll
            for (int nt = 0; nt < 8; nt++) {
                o[nt][0] *= c0f; o[nt][1] *= c0f;
                o[nt][2] *= c1f; o[nt][3] *= c1f;
            }
            __syncwarp();

            // ---- O += P V ----
            #pragma unroll
            for (int k8 = 0; k8 < 4; k8++) {
                int kb = k8*8;
                unsigned a[4];
                a[0] = __float_as_uint(Ps[(r0+g)*36 + kb + tig]);
                a[1] = __float_as_uint(Ps[(r0+g+8)*36 + kb + tig]);
                a[2] = __float_as_uint(Ps[(r0+g)*36 + kb + tig + 4]);
                a[3] = __float_as_uint(Ps[(r0+g+8)*36 + kb + tig + 4]);
                #pragma unroll
                for (int nt = 0; nt < 8; nt++) {
                    unsigned b0 = __float_as_uint(Vs[(kb+tig)*VS_STR + nt*8 + g]);
                    unsigned b1 = __float_as_uint(Vs[(kb+tig+4)*VS_STR + nt*8 + g]);
                    MMA_TF32(o[nt], a, b0, b1);
                }
            }
        }
        __syncthreads();   // all warps done with buf (c&1) before overwrite
    }

    // ---- write O (tf32-rounded for the out GEMM) ----
    int b = bh >> 4, h = bh & 15;
    float i0 = 1.f / l0, i1 = 1.f / l1;
    #pragma unroll
    for (int nt = 0; nt < 8; nt++) {
        int cb = h*64 + nt*8 + tig*2;
        *(float2*)(g_ao + ((long)(b*TT + rowA))*EE + cb) =
            make_float2(f2tff(o[nt][0]*i0), f2tff(o[nt][1]*i0));
        *(float2*)(g_ao + ((long)(b*TT + rowB))*EE + cb) =
            make_float2(f2tff(o[nt][2]*i1), f2tff(o[nt][3]*i1));
    }
}

// ---------------- launch ---------------------------------------------------
extern "C" void kernel_launch(void* const* d_in, const int* in_sizes, int n_in,
                              void* d_out, int out_size)
{
    const float* x     = (const float*)d_in[0];
    const int*   tok   = (const int*)  d_in[1];
    const float* qwih  = (const float*)d_in[2];
    const float* qwhh  = (const float*)d_in[3];
    const float* qlinw = (const float*)d_in[4];
    const float* kwih  = (const float*)d_in[5];
    const float* kwhh  = (const float*)d_in[6];
    const float* klinw = (const float*)d_in[7];
    const float* vemb  = (const float*)d_in[8];
    const float* qlnw  = (const float*)d_in[9];
    const float* qlnb  = (const float*)d_in[10];
    const float* klnw  = (const float*)d_in[11];
    const float* klnb  = (const float*)d_in[12];
    const float* outw  = (const float*)d_in[13];
    const float* outb  = (const float*)d_in[14];
    float* out = (float*)d_out;

    static cudaStream_t s1 = nullptr;
    static cudaEvent_t evA = nullptr, evB = nullptr, evC = nullptr;
    if (!s1) {
        cudaStreamCreateWithFlags(&s1, cudaStreamNonBlocking);
        cudaEventCreateWithFlags(&evA, cudaEventDisableTiming);
        cudaEventCreateWithFlags(&evB, cudaEventDisableTiming);
        cudaEventCreateWithFlags(&evC, cudaEventDisableTiming);
        cudaFuncSetAttribute(attn3_kernel,
                             cudaFuncAttributeMaxDynamicSharedMemorySize, ATT_SMEM);
    }

    wconv_kernel<<<dim3(1024, 3), 256>>>(qlinw, klinw, outw);
    prep_kernel<<<NROW, 256>>>(x, tok, vemb, qwih, kwih);

    cudaEventRecord(evA, 0);
    cudaStreamWaitEvent(s1, evA, 0);
    gru_kernel<<<4, 192, 0, s1>>>(qwhh, kwhh);            // side stream

    tgemm_qk_kernel<<<dim3(EE/128, NROW/128, 2), 256>>>(x);  // overlaps GRU
    cudaEventRecord(evB, 0);
    cudaStreamWaitEvent(s1, evB, 0);
    posgemm_kernel<<<dim3(8, 128, 2), 256, 0, s1>>>(qlinw, klinw);
    cudaEventRecord(evC, s1);
    cudaStreamWaitEvent(0, evC, 0);

    ln_kernel<<<2*NROW, 256>>>(qlnw, qlnb, klnw, klnb);
    attn3_kernel<<<dim3(TT/128, BB*HN), 256, ATT_SMEM>>>();
    tgemm_out_kernel<<<dim3(EE/128, NROW/128), 256>>>(outb, out);
}

// round 5
// speedup vs baseline: 2.0168x; 1.0142x over previous
#include <cuda_runtime.h>
#include <math.h>

#define EE 1024
#define HN 16
#define HDIM 64
#define DI 64
#define BB 2
#define TT 2048
#define NROW (BB*TT)   // 4096
#define G3 192
#define KP 960         // proj K

// ---------------- scratch (static device memory) ---------------------------
__device__ float g_proj[NROW*KP];       // tf32-rounded, shared by q/k
__device__ float g_xw_q[NROW*G3];
__device__ float g_xw_k[NROW*G3];
__device__ float g_pos_q[NROW*DI];
__device__ float g_pos_k[NROW*DI];
__device__ float g_vh[BB*HN*TT*HDIM];   // [bh][t][d] tf32
__device__ float g_qpre[NROW*EE];
__device__ float g_kpre[NROW*EE];
__device__ float g_qh[BB*HN*TT*HDIM];   // tf32
__device__ float g_kh[BB*HN*TT*HDIM];   // tf32
__device__ float g_ao[NROW*EE];         // tf32
__device__ float g_wq[EE*EE];           // tf32 weights
__device__ float g_wk[EE*EE];
__device__ float g_wo[EE*EE];

__device__ __forceinline__ unsigned f2tf(float x) {
    unsigned r;
    asm("cvt.rna.tf32.f32 %0, %1;" : "=r"(r) : "f"(x));
    return r;
}
__device__ __forceinline__ float f2tff(float x) { return __uint_as_float(f2tf(x)); }

#define MMA_TF32(d, a, b0, b1) \
    asm volatile("mma.sync.aligned.m16n8k8.row.col.f32.tf32.tf32.f32 " \
        "{%0,%1,%2,%3},{%4,%5,%6,%7},{%8,%9},{%0,%1,%2,%3};" \
        : "+f"((d)[0]), "+f"((d)[1]), "+f"((d)[2]), "+f"((d)[3]) \
        : "r"((a)[0]), "r"((a)[1]), "r"((a)[2]), "r"((a)[3]), "r"(b0), "r"(b1))

#define CPA16(dst_u32, src) \
    asm volatile("cp.async.cg.shared.global [%0], [%1], 16;" :: "r"(dst_u32), "l"(src))
#define CPCOMMIT() asm volatile("cp.async.commit_group;")
#define CPWAIT(n)  asm volatile("cp.async.wait_group %0;" :: "n"(n))

// packed f32x2 helpers
__device__ __forceinline__ unsigned long long packf2(float x, float y) {
    unsigned long long p;
    asm("mov.b64 %0, {%1, %2};" : "=l"(p) : "f"(x), "f"(y));
    return p;
}
__device__ __forceinline__ void unpackf2(unsigned long long p, float& x, float& y) {
    asm("mov.b64 {%0, %1}, %2;" : "=f"(x), "=f"(y) : "l"(p));
}
#define FMA2(acc, a, b) \
    asm("fma.rn.f32x2 %0, %1, %2, %0;" : "+l"(acc) : "l"(a), "l"(b))

// ---------------- weight convert to tf32 -----------------------------------
__global__ void __launch_bounds__(256) wconv_kernel(
    const float* __restrict__ qw, const float* __restrict__ kw,
    const float* __restrict__ ow)
{
    const float* src = blockIdx.y == 0 ? qw : (blockIdx.y == 1 ? kw : ow);
    float* dst = blockIdx.y == 0 ? g_wq : (blockIdx.y == 1 ? g_wk : g_wo);
    long i = ((long)blockIdx.x*256 + threadIdx.x)*4;
    float4 v = *(const float4*)(src + i);
    *(float4*)(dst + i) = make_float4(f2tff(v.x), f2tff(v.y), f2tff(v.z), f2tff(v.w));
}

// ---------------- prep_xw: pool(x) @ wih^T for both paths (tiny, first) ----
__global__ void __launch_bounds__(256) prep_xw_kernel(
    const float* __restrict__ x,
    const float* __restrict__ qwih, const float* __restrict__ kwih)
{
    __shared__ float xs[DI];
    int row = blockIdx.x;
    int tid = threadIdx.x;
    if (tid < DI) {
        const float* xp = x + (long)row*EE + tid*16;
        float s = 0.f;
        #pragma unroll
        for (int i = 0; i < 4; i++) {
            float4 v = ((const float4*)xp)[i];
            s += (v.x + v.y) + (v.z + v.w);
        }
        xs[tid] = s * (1.f/16.f);
    }
    __syncthreads();

    for (int idx = tid; idx < 2*G3; idx += 256) {
        int path = idx / G3, g = idx - path*G3;
        const float* w = (path ? kwih : qwih) + g*DI;
        float a0=0.f, a1=0.f, a2=0.f, a3=0.f;
        #pragma unroll
        for (int d = 0; d < DI; d += 4) {
            a0 += xs[d+0]*w[d+0];
            a1 += xs[d+1]*w[d+1];
            a2 += xs[d+2]*w[d+2];
            a3 += xs[d+3]*w[d+3];
        }
        float acc = (a0+a1)+(a2+a3);
        (path ? g_xw_k : g_xw_q)[(long)row*G3 + g] = acc;
    }
}

// ---------------- prep_main: v = silu(x)*emb, proj pool ---------------------
__global__ void __launch_bounds__(256) prep_main_kernel(
    const float* __restrict__ x, const int* __restrict__ tok,
    const float* __restrict__ vemb)
{
    __shared__ float xsh[EE];
    int row = blockIdx.x;
    int tid = threadIdx.x;
    int b = row >> 11, t = row & (TT-1);

    ((float4*)xsh)[tid] = ((const float4*)(x + (long)row*EE))[tid];
    __syncthreads();

    int tk = tok[row];
    const float* ve = vemb + (long)tk*EE;
    for (int c = tid; c < EE; c += 256) {
        float xc = xsh[c];
        float s = xc / (1.f + __expf(-xc));
        float val = s * ve[c];
        int h = c >> 6, d = c & 63;
        g_vh[((long)(b*HN + h)*TT + t)*HDIM + d] = f2tff(val);
    }

    for (int j = tid; j < KP; j += 256) {
        int s0 = (j*16)/15;
        int e0 = ((j+1)*16 + 14)/15;
        float s = 0.f;
        for (int c = s0; c < e0; c++) s += xsh[c];
        s *= 1.f/(float)(e0 - s0);
        g_proj[(long)row*KP + j] = f2tff(s);
    }
}

// ---------------- GRU: 128 thr/recurrence, 1 bar/step, f32x2 dots ----------
// thread pair (j = tid>>1, half = tid&1): partial dots for gates r,z,n of j
// over k in [half*32, half*32+32); combine via shfl_xor(1); even lane gates.
__global__ void __launch_bounds__(128, 1) gru_kernel(
    const float* __restrict__ qwhh, const float* __restrict__ kwhh)
{
    int path = blockIdx.x >> 1;
    int b = blockIdx.x & 1;
    int tid = threadIdx.x;
    int j = tid >> 1;
    int half = tid & 1;
    const float* W = (path ? kwhh : qwhh);
    const float* xw = (path ? g_xw_k : g_xw_q) + (long)b*TT*G3;
    float* pos = (path ? g_pos_k : g_pos_q) + (long)b*TT*DI;

    // weights in registers: 16 f32x2 per gate
    unsigned long long wr[16], wz[16], wn[16];
    {
        const float* pr = W + (long)j*DI + half*32;
        const float* pz = W + (long)(64+j)*DI + half*32;
        const float* pn = W + (long)(128+j)*DI + half*32;
        #pragma unroll
        for (int i = 0; i < 16; i++) {
            wr[i] = packf2(pr[2*i], pr[2*i+1]);
            wz[i] = packf2(pz[2*i], pz[2*i+1]);
            wn[i] = packf2(pn[2*i], pn[2*i+1]);
        }
    }

    __shared__ float hbuf[2][DI];
    if (tid < DI) { hbuf[0][tid] = 0.f; }
    __syncthreads();

    // xw prefetch (even lanes)
    float xr_p = 0.f, xz_p = 0.f, xn_p = 0.f;
    if (half == 0) {
        xr_p = xw[j];
        xz_p = xw[64 + j];
        xn_p = xw[128 + j];
    }

    for (int t = 0; t < TT; t++) {
        int cur = t & 1, nxt = cur ^ 1;
        float xr = xr_p, xz = xz_p, xn = xn_p;
        if (half == 0 && t + 1 < TT) {
            const float* nx = xw + (long)(t+1)*G3;
            xr_p = nx[j]; xz_p = nx[64 + j]; xn_p = nx[128 + j];
        }
        float hprev = hbuf[cur][j];   // even lane uses; cheap for all

        // load this half of h as f32x2 pairs
        const float4* hb4 = (const float4*)(hbuf[cur] + half*32);
        unsigned long long ar0 = 0ull, ar1 = 0ull;
        unsigned long long az0 = 0ull, az1 = 0ull;
        unsigned long long an0 = 0ull, an1 = 0ull;
        #pragma unroll
        for (int i = 0; i < 8; i++) {
            float4 hv = hb4[i];
            unsigned long long h01 = packf2(hv.x, hv.y);
            unsigned long long h23 = packf2(hv.z, hv.w);
            FMA2(ar0, h01, wr[2*i]);  FMA2(ar1, h23, wr[2*i+1]);
            FMA2(az0, h01, wz[2*i]);  FMA2(az1, h23, wz[2*i+1]);
            FMA2(an0, h01, wn[2*i]);  FMA2(an1, h23, wn[2*i+1]);
        }
        float a, bb2, c2, d2;
        unpackf2(ar0, a, bb2); unpackf2(ar1, c2, d2);
        float pr = (a + bb2) + (c2 + d2);
        unpackf2(az0, a, bb2); unpackf2(az1, c2, d2);
        float pz = (a + bb2) + (c2 + d2);
        unpackf2(an0, a, bb2); unpackf2(an1, c2, d2);
        float pn = (a + bb2) + (c2 + d2);

        pr += __shfl_xor_sync(0xffffffffu, pr, 1);
        pz += __shfl_xor_sync(0xffffffffu, pz, 1);
        pn += __shfl_xor_sync(0xffffffffu, pn, 1);

        if (half == 0) {
            float r = 1.f/(1.f + __expf(-(pr + xr)));
            float z = 1.f/(1.f + __expf(-(pz + xz)));
            float n = __tanhf(xn + r*pn);
            float hn = (1.f - z)*n + z*hprev;
            hbuf[nxt][j] = hn;
            pos[(long)t*DI + j] = hn;
        }
        __syncthreads();
    }
}

// ---------------- tf32 tensor-core GEMM: C = A @ W^T (+res)(+bias) ---------
template<bool RES, bool BIAS>
__device__ __forceinline__ void tgemm_body(
    const float* __restrict__ A, int lda,
    const float* __restrict__ W, int ldw,
    const float* __restrict__ res, const float* __restrict__ bias,
    float* __restrict__ C, int N, int NK)
{
    __shared__ float As[2][128*20];
    __shared__ float Bs[2][128*20];
    int tid = threadIdx.x;
    int m0 = blockIdx.y * 128, n0 = blockIdx.x * 128;
    int wid = tid >> 5, lane = tid & 31;
    int g = lane >> 2, tig = lane & 3;
    int wm = (wid >> 2) * 64, wn = (wid & 3) * 32;
    int lrow = tid >> 2, lc = (tid & 3) * 4;

    const float* Ap = A + (long)(m0 + lrow)*lda + lc;
    const float* Wp = W + (long)(n0 + lrow)*ldw + lc;

    float4 ra0 = *(const float4*)(Ap);
    float4 ra1 = *(const float4*)(Ap + (long)64*lda);
    float4 rb0 = *(const float4*)(Wp);
    float4 rb1 = *(const float4*)(Wp + (long)64*ldw);

    float acc[4][4][4] = {};
    int buf = 0;
    for (int kt = 0; kt < NK; kt++) {
        float* Asb = As[buf];
        float* Bsb = Bs[buf];
        *(float4*)(Asb + lrow*20 + lc) = ra0;
        *(float4*)(Asb + (lrow+64)*20 + lc) = ra1;
        *(float4*)(Bsb + lrow*20 + lc) = rb0;
        *(float4*)(Bsb + (lrow+64)*20 + lc) = rb1;
        __syncthreads();
        if (kt + 1 < NK) {
            int ko = (kt+1)*16;
            ra0 = *(const float4*)(Ap + ko);
            ra1 = *(const float4*)(Ap + (long)64*lda + ko);
            rb0 = *(const float4*)(Wp + ko);
            rb1 = *(const float4*)(Wp + (long)64*ldw + ko);
        }
        #pragma unroll
        for (int kk = 0; kk < 16; kk += 8) {
            unsigned a[4][4], b[4][2];
            #pragma unroll
            for (int mt = 0; mt < 4; mt++) {
                int r = wm + mt*16 + g;
                a[mt][0] = __float_as_uint(Asb[r*20 + kk + tig]);
                a[mt][1] = __float_as_uint(Asb[(r+8)*20 + kk + tig]);
                a[mt][2] = __float_as_uint(Asb[r*20 + kk + tig + 4]);
                a[mt][3] = __float_as_uint(Asb[(r+8)*20 + kk + tig + 4]);
            }
            #pragma unroll
            for (int nt = 0; nt < 4; nt++) {
                int r = wn + nt*8 + g;
                b[nt][0] = __float_as_uint(Bsb[r*20 + kk + tig]);
                b[nt][1] = __float_as_uint(Bsb[r*20 + kk + tig + 4]);
            }
            #pragma unroll
            for (int mt = 0; mt < 4; mt++)
                #pragma unroll
                for (int nt = 0; nt < 4; nt++)
                    MMA_TF32(acc[mt][nt], a[mt], b[nt][0], b[nt][1]);
        }
        buf ^= 1;
    }

    #pragma unroll
    for (int mt = 0; mt < 4; mt++) {
        #pragma unroll
        for (int nt = 0; nt < 4; nt++) {
            long r0 = m0 + wm + mt*16 + g;
            long r1 = r0 + 8;
            long cb = n0 + wn + nt*8 + tig*2;
            float v0 = acc[mt][nt][0], v1 = acc[mt][nt][1];
            float v2 = acc[mt][nt][2], v3 = acc[mt][nt][3];
            if (RES) {
                float2 e0 = *(const float2*)(res + r0*N + cb);
                float2 e1 = *(const float2*)(res + r1*N + cb);
                v0 += e0.x; v1 += e0.y; v2 += e1.x; v3 += e1.y;
            }
            if (BIAS) {
                v0 += bias[cb]; v1 += bias[cb+1];
                v2 += bias[cb]; v3 += bias[cb+1];
            }
            *(float2*)(C + r0*N + cb) = make_float2(v0, v1);
            *(float2*)(C + r1*N + cb) = make_float2(v2, v3);
        }
    }
}

__global__ void __launch_bounds__(256) tgemm_qk_kernel(const float* __restrict__ x)
{
    int z = blockIdx.z;
    tgemm_body<true,false>(g_proj, KP, (z ? g_wk : g_wq) + DI, EE, x, nullptr,
                           z ? g_kpre : g_qpre, EE, KP/16);
}

__global__ void __launch_bounds__(256) tgemm_out_kernel(
    const float* __restrict__ bias, float* __restrict__ C)
{
    tgemm_body<false,true>(g_ao, EE, g_wo, EE, nullptr, bias, C, EE, EE/16);
}

// ---------------- pos small GEMM: C += pos @ Wpos^T (K=64, fp32) -----------
__global__ void __launch_bounds__(256) posgemm_kernel(
    const float* __restrict__ qw, const float* __restrict__ kw)
{
    int path = blockIdx.z;
    const float* pos = path ? g_pos_k : g_pos_q;
    const float* W = path ? kw : qw;
    float* C = path ? g_kpre : g_qpre;
    __shared__ float Wt[64][132];
    __shared__ float Ps_[32][68];
    int n0 = blockIdx.x * 128;
    int m0 = blockIdx.y * 32;
    int tid = threadIdx.x;

    for (int i = tid; i < 128*16; i += 256) {
        int r = i >> 4, c4 = (i & 15)*4;
        float4 v = *(const float4*)(W + (long)(n0 + r)*EE + c4);
        Wt[c4+0][r] = v.x; Wt[c4+1][r] = v.y; Wt[c4+2][r] = v.z; Wt[c4+3][r] = v.w;
    }
    for (int i = tid; i < 32*16; i += 256) {
        int r = i >> 4, c4 = (i & 15)*4;
        *(float4*)&Ps_[r][c4] = *(const float4*)(pos + (long)(m0 + r)*DI + c4);
    }
    __syncthreads();

    int tx = tid & 15, ty = tid >> 4;
    int r0 = ty*2, c0 = tx*8;
    float acc[2][8] = {};
    #pragma unroll
    for (int k = 0; k < 64; k++) {
        float p0 = Ps_[r0][k], p1 = Ps_[r0+1][k];
        float4 w0 = *(float4*)&Wt[k][c0];
        float4 w1 = *(float4*)&Wt[k][c0+4];
        acc[0][0] += p0*w0.x; acc[0][1] += p0*w0.y; acc[0][2] += p0*w0.z; acc[0][3] += p0*w0.w;
        acc[0][4] += p0*w1.x; acc[0][5] += p0*w1.y; acc[0][6] += p0*w1.z; acc[0][7] += p0*w1.w;
        acc[1][0] += p1*w0.x; acc[1][1] += p1*w0.y; acc[1][2] += p1*w0.z; acc[1][3] += p1*w0.w;
        acc[1][4] += p1*w1.x; acc[1][5] += p1*w1.y; acc[1][6] += p1*w1.z; acc[1][7] += p1*w1.w;
    }
    #pragma unroll
    for (int i = 0; i < 2; i++) {
        long m = m0 + r0 + i;
        #pragma unroll
        for (int j = 0; j < 8; j += 4) {
            float4 old = *(float4*)(C + m*EE + n0 + c0 + j);
            old.x += acc[i][j]; old.y += acc[i][j+1];
            old.z += acc[i][j+2]; old.w += acc[i][j+3];
            *(float4*)(C + m*EE + n0 + c0 + j) = old;
        }
    }
}

// ---------------- LayerNorm -> head-major [bh][t][d], tf32-rounded ---------
__global__ void __launch_bounds__(256) ln_kernel(
    const float* __restrict__ wq, const float* __restrict__ bq,
    const float* __restrict__ wk, const float* __restrict__ bk)
{
    int idx = blockIdx.x;
    int path = idx >> 12;
    int row = idx & 4095;
    const float* src = (path ? g_kpre : g_qpre) + (long)row*EE;
    const float* w = path ? wk : wq;
    const float* bb = path ? bk : bq;
    float* dst = path ? g_kh : g_qh;
    int tid = threadIdx.x;

    float4 v = ((const float4*)src)[tid];
    float s  = v.x + v.y + v.z + v.w;
    float sq = v.x*v.x + v.y*v.y + v.z*v.z + v.w*v.w;
    #pragma unroll
    for (int o = 16; o; o >>= 1) {
        s  += __shfl_xor_sync(0xffffffffu, s,  o);
        sq += __shfl_xor_sync(0xffffffffu, sq, o);
    }
    __shared__ float ss[8], sqs[8];
    __shared__ float mu_s, r_s;
    if ((tid & 31) == 0) { ss[tid >> 5] = s; sqs[tid >> 5] = sq; }
    __syncthreads();
    if (tid == 0) {
        float S = 0.f, SQ = 0.f;
        #pragma unroll
        for (int i = 0; i < 8; i++) { S += ss[i]; SQ += sqs[i]; }
        float mu = S * (1.f/EE);
        float var = SQ * (1.f/EE) - mu*mu;
        mu_s = mu;
        r_s = rsqrtf(var + 1e-5f);
    }
    __syncthreads();
    float mu = mu_s, r = r_s;
    int b = row >> 11, t = row & (TT-1);
    int c0 = tid * 4;
    int h = c0 >> 6, d = c0 & 63;
    float4 o;
    o.x = f2tff((v.x - mu)*r*w[c0+0] + bb[c0+0]);
    o.y = f2tff((v.y - mu)*r*w[c0+1] + bb[c0+1]);
    o.z = f2tff((v.z - mu)*r*w[c0+2] + bb[c0+2]);
    o.w = f2tff((v.w - mu)*r*w[c0+3] + bb[c0+3]);
    *(float4*)&dst[((long)(b*HN + h)*TT + t)*HDIM + d] = o;
}

// ---------------- tf32 flash attention, cp.async double-buffered -----------
#define KS_STR 68
#define VS_STR 72
#define KV_BUF 4480
#define PS_OFF 8960
#define ATT_SMEM ((8960 + 128*36)*4)

__device__ __forceinline__ void attn_issue(
    float* sm, int buf, int s0, int tid,
    const float* kbase, const float* vbase)
{
    float* Kb = sm + buf*KV_BUF;
    float* Vb = Kb + 32*KS_STR;
    #pragma unroll
    for (int i = 0; i < 2; i++) {
        int f = tid + i*256;
        int rr = f >> 4, c4 = (f & 15) * 4;
        unsigned kd = (unsigned)__cvta_generic_to_shared(Kb + rr*KS_STR + c4);
        unsigned vd = (unsigned)__cvta_generic_to_shared(Vb + rr*VS_STR + c4);
        CPA16(kd, kbase + (long)(s0 + rr)*HDIM + c4);
        CPA16(vd, vbase + (long)(s0 + rr)*HDIM + c4);
    }
}

__global__ void __launch_bounds__(256) attn3_kernel()
{
    extern __shared__ float sm[];
    float* Qs = sm;
    float* Ps = sm + PS_OFF;

    int bh = blockIdx.y;
    int qblk = (int)gridDim.x - 1 - (int)blockIdx.x;
    int qr0 = qblk * 128;
    int tid = threadIdx.x;
    int wid = tid >> 5, lane = tid & 31;
    int g = lane >> 2, tig = lane & 3;
    int r0 = wid * 16;

    const float* qbase = g_qh + (long)bh*TT*HDIM;
    const float* kbase = g_kh + (long)bh*TT*HDIM;
    const float* vbase = g_vh + (long)bh*TT*HDIM;

    #pragma unroll
    for (int i = 0; i < 8; i++) {
        int f = tid + i*256;
        int rr = f >> 4, c4 = (f & 15) * 4;
        *(float4*)(Qs + rr*KS_STR + c4) =
            *(const float4*)(qbase + (long)(qr0 + rr)*HDIM + c4);
    }
    __syncthreads();
    unsigned qf[8][4];
    #pragma unroll
    for (int k8 = 0; k8 < 8; k8++) {
        int kb = k8*8;
        qf[k8][0] = __float_as_uint(Qs[(r0+g)*KS_STR + kb + tig]);
        qf[k8][1] = __float_as_uint(Qs[(r0+g+8)*KS_STR + kb + tig]);
        qf[k8][2] = __float_as_uint(Qs[(r0+g)*KS_STR + kb + tig + 4]);
        qf[k8][3] = __float_as_uint(Qs[(r0+g+8)*KS_STR + kb + tig + 4]);
    }
    __syncthreads();

    float o[8][4] = {};
    float m0 = -1e30f, m1 = -1e30f, l0 = 0.f, l1 = 0.f;
    int rowA = qr0 + r0 + g;
    int rowB = rowA + 8;
    int wrow_lo = qr0 + r0;
    int wrow_hi = wrow_lo + 15;

    int nchunk = 4 * (qblk + 1);
    attn_issue(sm, 0, 0, tid, kbase, vbase);
    CPCOMMIT();

    for (int c = 0; c < nchunk; c++) {
        int s0 = c * 32;
        if (c + 1 < nchunk) {
            attn_issue(sm, (c+1) & 1, s0 + 32, tid, kbase, vbase);
            CPCOMMIT();
            CPWAIT(1);
        } else {
            CPWAIT(0);
        }
        __syncthreads();

        if (s0 <= wrow_hi) {
            float* Ks = sm + (c & 1)*KV_BUF;
            float* Vs = Ks + 32*KS_STR;

            float sacc[4][4] = {};
            #pragma unroll
            for (int k8 = 0; k8 < 8; k8++) {
                int kb = k8*8;
                #pragma unroll
                for (int nt = 0; nt < 4; nt++) {
                    int rr = nt*8 + g;
                    unsigned b0 = __float_as_uint(Ks[rr*KS_STR + kb + tig]);
                    unsigned b1 = __float_as_uint(Ks[rr*KS_STR + kb + tig + 4]);
                    MMA_TF32(sacc[nt], qf[k8], b0, b1);
                }
            }

            bool needmask = (s0 + 31 > wrow_lo);
            #pragma unroll
            for (int nt = 0; nt < 4; nt++) {
                int col0 = s0 + nt*8 + tig*2;
                float v0 = sacc[nt][0]*0.25f, v1 = sacc[nt][1]*0.25f;
                float v2 = sacc[nt][2]*0.25f, v3 = sacc[nt][3]*0.25f;
                if (needmask) {
                    if (col0     > rowA) v0 = -1e30f;
                    if (col0 + 1 > rowA) v1 = -1e30f;
                    if (col0     > rowB) v2 = -1e30f;
                    if (col0 + 1 > rowB) v3 = -1e30f;
                }
                sacc[nt][0] = v0; sacc[nt][1] = v1; sacc[nt][2] = v2; sacc[nt][3] = v3;
            }

            float rm0 = -1e30f, rm1 = -1e30f;
            #pragma unroll
            for (int nt = 0; nt < 4; nt++) {
                rm0 = fmaxf(rm0, fmaxf(sacc[nt][0], sacc[nt][1]));
                rm1 = fmaxf(rm1, fmaxf(sacc[nt][2], sacc[nt][3]));
            }
            rm0 = fmaxf(rm0, __shfl_xor_sync(0xffffffffu, rm0, 1));
            rm0 = fmaxf(rm0, __shfl_xor_sync(0xffffffffu, rm0, 2));
            rm1 = fmaxf(rm1, __shfl_xor_sync(0xffffffffu, rm1, 1));
            rm1 = fmaxf(rm1, __shfl_xor_sync(0xffffffffu, rm1, 2));
            float mn0 = fmaxf(m0, rm0), mn1 = fmaxf(m1, rm1);
            float c0f = __expf(m0 - mn0), c1f = __expf(m1 - mn1);
            m0 = mn0; m1 = mn1;

            float ps0 = 0.f, ps1 = 0.f;
            #pragma unroll
            for (int nt = 0; nt < 4; nt++) {
                float p0 = __expf(sacc[nt][0] - mn0);
                float p1 = __expf(sacc[nt][1] - mn0);
                float p2 = __expf(sacc[nt][2] - mn1);
                float p3 = __expf(sacc[nt][3] - mn1);
                ps0 += p0 + p1; ps1 += p2 + p3;
                int cb = nt*8 + tig*2;
                *(float2*)(Ps + (r0+g)*36 + cb)   = make_float2(f2tff(p0), f2tff(p1));
                *(float2*)(Ps + (r0+g+8)*36 + cb) = make_float2(f2tff(p2), f2tff(p3));
            }
            ps0 += __shfl_xor_sync(0xffffffffu, ps0, 1);
            ps0 += __shfl_xor_sync(0xffffffffu, ps0, 2);
            ps1 += __shfl_xor_sync(0xffffffffu, ps1, 1);
            ps1 += __shfl_xor_sync(0xffffffffu, ps1, 2);
            l0 = l0*c0f + ps0;
            l1 = l1*c1f + ps1;

            #pragma unroll
            for (int nt = 0; nt < 8; nt++) {
                o[nt][0] *= c0f; o[nt][1] *= c0f;
                o[nt][2] *= c1f; o[nt][3] *= c1f;
            }
            __syncwarp();

            #pragma unroll
            for (int k8 = 0; k8 < 4; k8++) {
                int kb = k8*8;
                unsigned a[4];
                a[0] = __float_as_uint(Ps[(r0+g)*36 + kb + tig]);
                a[1] = __float_as_uint(Ps[(r0+g+8)*36 + kb + tig]);
                a[2] = __float_as_uint(Ps[(r0+g)*36 + kb + tig + 4]);
                a[3] = __float_as_uint(Ps[(r0+g+8)*36 + kb + tig + 4]);
                #pragma unroll
                for (int nt = 0; nt < 8; nt++) {
                    unsigned b0 = __float_as_uint(Vs[(kb+tig)*VS_STR + nt*8 + g]);
                    unsigned b1 = __float_as_uint(Vs[(kb+tig+4)*VS_STR + nt*8 + g]);
                    MMA_TF32(o[nt], a, b0, b1);
                }
            }
        }
        __syncthreads();
    }

    int b = bh >> 4, h = bh & 15;
    float i0 = 1.f / l0, i1 = 1.f / l1;
    #pragma unroll
    for (int nt = 0; nt < 8; nt++) {
        int cb = h*64 + nt*8 + tig*2;
        *(float2*)(g_ao + ((long)(b*TT + rowA))*EE + cb) =
            make_float2(f2tff(o[nt][0]*i0), f2tff(o[nt][1]*i0));
        *(float2*)(g_ao + ((long)(b*TT + rowB))*EE + cb) =
            make_float2(f2tff(o[nt][2]*i1), f2tff(o[nt][3]*i1));
    }
}

// ---------------- launch ---------------------------------------------------
extern "C" void kernel_launch(void* const* d_in, const int* in_sizes, int n_in,
                              void* d_out, int out_size)
{
    const float* x     = (const float*)d_in[0];
    const int*   tok   = (const int*)  d_in[1];
    const float* qwih  = (const float*)d_in[2];
    const float* qwhh  = (const float*)d_in[3];
    const float* qlinw = (const float*)d_in[4];
    const float* kwih  = (const float*)d_in[5];
    const float* kwhh  = (const float*)d_in[6];
    const float* klinw = (const float*)d_in[7];
    const float* vemb  = (const float*)d_in[8];
    const float* qlnw  = (const float*)d_in[9];
    const float* qlnb  = (const float*)d_in[10];
    const float* klnw  = (const float*)d_in[11];
    const float* klnb  = (const float*)d_in[12];
    const float* outw  = (const float*)d_in[13];
    const float* outb  = (const float*)d_in[14];
    float* out = (float*)d_out;

    static cudaStream_t s1 = nullptr;
    static cudaEvent_t evA = nullptr, evG = nullptr;
    if (!s1) {
        cudaStreamCreateWithFlags(&s1, cudaStreamNonBlocking);
        cudaEventCreateWithFlags(&evA, cudaEventDisableTiming);
        cudaEventCreateWithFlags(&evG, cudaEventDisableTiming);
        cudaFuncSetAttribute(attn3_kernel,
                             cudaFuncAttributeMaxDynamicSharedMemorySize, ATT_SMEM);
    }

    wconv_kernel<<<dim3(1024, 3), 256>>>(qlinw, klinw, outw);   // #1
    prep_xw_kernel<<<NROW, 256>>>(x, qwih, kwih);               // #2
    cudaEventRecord(evA, 0);
    prep_main_kernel<<<NROW, 256>>>(x, tok, vemb);              // #3
    cudaStreamWaitEvent(s1, evA, 0);
    gru_kernel<<<4, 128, 0, s1>>>(qwhh, kwhh);                  // #4 (profiled)
    tgemm_qk_kernel<<<dim3(EE/128, NROW/128, 2), 256>>>(x);     // #5, overlaps GRU
    cudaEventRecord(evG, s1);
    cudaStreamWaitEvent(0, evG, 0);
    posgemm_kernel<<<dim3(8, 128, 2), 256>>>(qlinw, klinw);     // #6
    ln_kernel<<<2*NROW, 256>>>(qlnw, qlnb, klnw, klnb);         // #7
    attn3_kernel<<<dim3(TT/128, BB*HN), 256, ATT_SMEM>>>();     // #8
    tgemm_out_kernel<<<dim3(EE/128, NROW/128), 256>>>(outb, out); // #9
}